// round 3
// baseline (speedup 1.0000x reference)
#include <cuda_runtime.h>

#define NN 100000
#define EE 1600000
#define D  128
#define OD 64
#define NG 512

// Scratch (device globals: allocation-free). 16B-aligned for v4 RED.
__device__ __align__(16) float g_bufA[NN * D];   // h_hat messages
__device__ __align__(16) float g_bufB[NN * D];   // accumulator (init = self-loop)
__device__ float g_deg[NN];
__device__ float g_dinv[NN];
__device__ __align__(16) float g_pool[NG * D];

__device__ __forceinline__ void red_add_v4(float* addr, float4 v) {
    asm volatile("red.global.add.v4.f32 [%0], {%1,%2,%3,%4};"
                 :: "l"(__cvta_generic_to_global(addr)),
                    "f"(v.x), "f"(v.y), "f"(v.z), "f"(v.w)
                 : "memory");
}

// ---------------------------------------------------------------------------
__global__ void k_init() {
    int i = blockIdx.x * blockDim.x + threadIdx.x;
    if (i < NN) g_deg[i] = 1.0f;          // self-loop
    if (i < NG * D) g_pool[i] = 0.0f;
}

__global__ void k_deg(const int* __restrict__ ei) {
    int i = blockIdx.x * blockDim.x + threadIdx.x;
    if (i < EE) {
        int dst = ei[EE + i];
        atomicAdd(&g_deg[dst], 1.0f);
    }
}

__global__ void k_dinv() {
    int i = blockIdx.x * blockDim.x + threadIdx.x;
    if (i < NN) g_dinv[i] = rsqrtf(g_deg[i]);
}

// ---------------------------------------------------------------------------
// GEMM: out = dinv[row] * (in @ W)  written to BOTH g_bufA and g_bufB.
// FUSE=false: in = X param (layer 1 input x).
// FUSE=true : in = relu(dinv[row]*g_bufB[row] + b_in)  (finishes previous conv)
// Tile: 128x128 per block, BK=32, 256 threads, 8x8 register tile per thread.
template<bool FUSE>
__global__ void __launch_bounds__(256)
k_gemm(const float* __restrict__ X, const float* __restrict__ W,
       const float* __restrict__ bin) {
    __shared__ float As[32 * 128];   // [k][row]  (transposed)
    __shared__ float Bs[32 * 128];   // [k][col]

    const int t  = threadIdx.x;
    const int tx = t & 15;           // col group (8 cols)
    const int ty = t >> 4;           // row group (8 rows)
    const int row0 = blockIdx.x * 128;

    const float4* X4 = FUSE ? reinterpret_cast<const float4*>(g_bufB)
                            : reinterpret_cast<const float4*>(X);
    const float4* W4 = reinterpret_cast<const float4*>(W);

    float acc[8][8];
    #pragma unroll
    for (int i = 0; i < 8; i++)
        #pragma unroll
        for (int j = 0; j < 8; j++) acc[i][j] = 0.0f;

    for (int k0 = 0; k0 < 128; k0 += 32) {
        // Load A tile (transposed into As[k][r])
        #pragma unroll
        for (int i = 0; i < 4; i++) {
            int id = t + i * 256;        // 0..1023
            int r  = id & 127;
            int q  = id >> 7;            // 0..7 (float4 within 32-wide k chunk)
            int grow = row0 + r;
            float4 v = make_float4(0.f, 0.f, 0.f, 0.f);
            if (grow < NN) {
                v = X4[grow * 32 + (k0 >> 2) + q];
                if (FUSE) {
                    float dv = g_dinv[grow];
                    int kk = k0 + q * 4;
                    v.x = fmaxf(fmaf(dv, v.x, bin[kk + 0]), 0.f);
                    v.y = fmaxf(fmaf(dv, v.y, bin[kk + 1]), 0.f);
                    v.z = fmaxf(fmaf(dv, v.z, bin[kk + 2]), 0.f);
                    v.w = fmaxf(fmaf(dv, v.w, bin[kk + 3]), 0.f);
                }
            }
            As[(q * 4 + 0) * 128 + r] = v.x;
            As[(q * 4 + 1) * 128 + r] = v.y;
            As[(q * 4 + 2) * 128 + r] = v.z;
            As[(q * 4 + 3) * 128 + r] = v.w;
        }
        // Load B tile (row-major copy)
        #pragma unroll
        for (int i = 0; i < 4; i++) {
            int id = t + i * 256;
            int kr = id >> 5;            // 0..31
            int qc = id & 31;            // float4 col
            reinterpret_cast<float4*>(Bs)[kr * 32 + qc] = W4[(k0 + kr) * 32 + qc];
        }
        __syncthreads();

        #pragma unroll 4
        for (int k = 0; k < 32; k++) {
            float4 a0 = reinterpret_cast<float4*>(As)[k * 32 + ty * 2];
            float4 a1 = reinterpret_cast<float4*>(As)[k * 32 + ty * 2 + 1];
            float4 b0 = reinterpret_cast<float4*>(Bs)[k * 32 + tx * 2];
            float4 b1 = reinterpret_cast<float4*>(Bs)[k * 32 + tx * 2 + 1];
            float a[8] = {a0.x, a0.y, a0.z, a0.w, a1.x, a1.y, a1.z, a1.w};
            float b[8] = {b0.x, b0.y, b0.z, b0.w, b1.x, b1.y, b1.z, b1.w};
            #pragma unroll
            for (int i = 0; i < 8; i++)
                #pragma unroll
                for (int j = 0; j < 8; j++)
                    acc[i][j] = fmaf(a[i], b[j], acc[i][j]);
        }
        __syncthreads();
    }

    // Epilogue: scale by dinv[row], write h_hat to bufA (messages) and
    // bufB (self-loop init of accumulator).
    const int c4 = tx * 2;  // float4 column index
    #pragma unroll
    for (int i = 0; i < 8; i++) {
        int grow = row0 + ty * 8 + i;
        if (grow < NN) {
            float dv = g_dinv[grow];
            float4 v0 = make_float4(acc[i][0] * dv, acc[i][1] * dv,
                                    acc[i][2] * dv, acc[i][3] * dv);
            float4 v1 = make_float4(acc[i][4] * dv, acc[i][5] * dv,
                                    acc[i][6] * dv, acc[i][7] * dv);
            float4* oa = reinterpret_cast<float4*>(g_bufA) + grow * 32 + c4;
            float4* ob = reinterpret_cast<float4*>(g_bufB) + grow * 32 + c4;
            oa[0] = v0; oa[1] = v1;
            ob[0] = v0; ob[1] = v1;
        }
    }
}

// ---------------------------------------------------------------------------
// Edge scatter: bufB[dst] += bufA[src].  One warp per edge, float4 vector RED.
__global__ void k_scatter(const int* __restrict__ ei) {
    long long gt = (long long)blockIdx.x * blockDim.x + threadIdx.x;
    int e = (int)(gt >> 5);
    int lane = (int)(gt & 31);
    if (e >= EE) return;
    int s = ei[e];
    int d = ei[EE + e];
    float4 v = reinterpret_cast<const float4*>(g_bufA)[s * 32 + lane];
    red_add_v4(g_bufB + (long long)d * D + lane * 4, v);
}

// ---------------------------------------------------------------------------
// Pool: pool[batch[n]] += relu(dinv[n]*bufB[n] + b2)
__global__ void k_pool(const int* __restrict__ batch,
                       const float* __restrict__ b2) {
    long long gt = (long long)blockIdx.x * blockDim.x + threadIdx.x;
    int n = (int)(gt >> 5);
    int lane = (int)(gt & 31);
    if (n >= NN) return;
    int g = batch[n];
    float dv = g_dinv[n];
    float4 v  = reinterpret_cast<const float4*>(g_bufB)[n * 32 + lane];
    float4 bb = reinterpret_cast<const float4*>(b2)[lane];
    float4 r;
    r.x = fmaxf(fmaf(dv, v.x, bb.x), 0.f);
    r.y = fmaxf(fmaf(dv, v.y, bb.y), 0.f);
    r.z = fmaxf(fmaf(dv, v.z, bb.z), 0.f);
    r.w = fmaxf(fmaf(dv, v.w, bb.w), 0.f);
    red_add_v4(g_pool + g * D + lane * 4, r);
}

// ---------------------------------------------------------------------------
// Head: out[g] = pool[g] @ Wl + bl   (512 x 64, K=128)
__global__ void k_final(const float* __restrict__ Wl,
                        const float* __restrict__ bl,
                        float* __restrict__ out) {
    __shared__ float p[D];
    int g = blockIdx.x;
    int o = threadIdx.x;  // 0..63
    p[o]      = g_pool[g * D + o];
    p[o + 64] = g_pool[g * D + o + 64];
    __syncthreads();
    float acc = bl[o];
    #pragma unroll 8
    for (int c = 0; c < D; c++)
        acc = fmaf(p[c], Wl[c * OD + o], acc);
    out[g * OD + o] = acc;
}

// ---------------------------------------------------------------------------
extern "C" void kernel_launch(void* const* d_in, const int* in_sizes, int n_in,
                              void* d_out, int out_size) {
    const float* x     = (const float*)d_in[0];
    const int*   ei    = (const int*)d_in[1];      // int32! (JAX x64 disabled)
    const int*   batch = (const int*)d_in[2];      // int32!
    const float* W1    = (const float*)d_in[3];
    const float* b1    = (const float*)d_in[4];
    const float* W2    = (const float*)d_in[5];
    const float* b2    = (const float*)d_in[6];
    const float* Wl    = (const float*)d_in[7];
    const float* bl    = (const float*)d_in[8];
    float* out = (float*)d_out;

    k_init<<<(NN + 255) / 256, 256>>>();
    k_deg <<<(EE + 255) / 256, 256>>>(ei);
    k_dinv<<<(NN + 255) / 256, 256>>>();

    // Layer 1: h_hat1 = dinv * (x @ W1); bufB = self-loop init; scatter edges
    k_gemm<false><<<(NN + 127) / 128, 256>>>(x, W1, nullptr);
    k_scatter<<<(int)(((long long)EE * 32 + 255) / 256), 256>>>(ei);

    // Layer 2: input = relu(dinv*bufB + b1) fused into GEMM load
    k_gemm<true><<<(NN + 127) / 128, 256>>>(nullptr, W2, b1);
    k_scatter<<<(int)(((long long)EE * 32 + 255) / 256), 256>>>(ei);

    // Pool (applies dinv*bufB + b2, relu) then head
    k_pool<<<(int)(((long long)NN * 32 + 255) / 256), 256>>>(batch, b2);
    k_final<<<NG, OD>>>(Wl, bl, out);
}

// round 5
// speedup vs baseline: 1.7727x; 1.7727x over previous
#include <cuda_runtime.h>

#define NN 100000
#define EE 1600000
#define D  128
#define OD 64
#define NG 512
#define SCAN_BLK 512
#define NBLK ((NN + SCAN_BLK - 1) / SCAN_BLK)   // 196

// Scratch (device globals: allocation-free)
__device__ __align__(16) float g_bufA[NN * D];   // h_hat messages
__device__ __align__(16) float g_bufB[NN * D];   // aggregated raw sums
__device__ float g_dinv[NN];
__device__ __align__(16) float g_pool[NG * D];
__device__ int   g_cnt[NN];          // in-degree (excl self)
__device__ int   g_pos[NN];          // fill cursors
__device__ int   g_rowptr[NN + 1];
__device__ int   g_blksum[256];
__device__ int   g_csr[EE];          // src ids grouped by dst

__device__ __forceinline__ void red_add_v4(float* addr, float4 v) {
    asm volatile("red.global.add.v4.f32 [%0], {%1,%2,%3,%4};"
                 :: "l"(__cvta_generic_to_global(addr)),
                    "f"(v.x), "f"(v.y), "f"(v.z), "f"(v.w)
                 : "memory");
}

// ---------------------------------------------------------------------------
__global__ void k_init() {
    int i = blockIdx.x * blockDim.x + threadIdx.x;
    if (i < NN) { g_cnt[i] = 0; g_pos[i] = 0; }
    if (i < NG * D) g_pool[i] = 0.0f;
}

__global__ void k_count(const int* __restrict__ ei) {
    int i = blockIdx.x * blockDim.x + threadIdx.x;
    if (i < EE) atomicAdd(&g_cnt[ei[EE + i]], 1);
}

// 3-kernel exclusive scan of g_cnt -> g_rowptr
__global__ void k_scan1() {
    __shared__ int s[SCAN_BLK];
    int gid = blockIdx.x * SCAN_BLK + threadIdx.x;
    int v = (gid < NN) ? g_cnt[gid] : 0;
    s[threadIdx.x] = v;
    __syncthreads();
    #pragma unroll
    for (int off = 1; off < SCAN_BLK; off <<= 1) {
        int t = (threadIdx.x >= off) ? s[threadIdx.x - off] : 0;
        __syncthreads();
        s[threadIdx.x] += t;
        __syncthreads();
    }
    if (gid < NN) g_rowptr[gid + 1] = s[threadIdx.x];   // inclusive, pre-offset
    if (threadIdx.x == SCAN_BLK - 1) g_blksum[blockIdx.x] = s[threadIdx.x];
    if (gid == 0) g_rowptr[0] = 0;
}

__global__ void k_scan2() {   // single block, 256 threads
    __shared__ int s[256];
    int v = (threadIdx.x < NBLK) ? g_blksum[threadIdx.x] : 0;
    s[threadIdx.x] = v;
    __syncthreads();
    #pragma unroll
    for (int off = 1; off < 256; off <<= 1) {
        int t = (threadIdx.x >= off) ? s[threadIdx.x - off] : 0;
        __syncthreads();
        s[threadIdx.x] += t;
        __syncthreads();
    }
    if (threadIdx.x < NBLK) g_blksum[threadIdx.x] = s[threadIdx.x] - v; // exclusive
}

__global__ void k_scan3() {
    int gid = blockIdx.x * SCAN_BLK + threadIdx.x;
    if (gid < NN) g_rowptr[gid + 1] += g_blksum[blockIdx.x];
}

__global__ void k_dinv() {
    int i = blockIdx.x * blockDim.x + threadIdx.x;
    if (i < NN) g_dinv[i] = rsqrtf((float)(g_cnt[i] + 1));   // +1 self-loop
}

__global__ void k_fill(const int* __restrict__ ei) {
    int i = blockIdx.x * blockDim.x + threadIdx.x;
    if (i < EE) {
        int s = ei[i];
        int d = ei[EE + i];
        int slot = g_rowptr[d] + atomicAdd(&g_pos[d], 1);
        g_csr[slot] = s;
    }
}

// ---------------------------------------------------------------------------
// GEMM: bufA = dinv[row] * (in @ W).
// FUSE=false: in = X (layer 1). FUSE=true: in = relu(dinv*bufB + b_in).
template<bool FUSE>
__global__ void __launch_bounds__(256)
k_gemm(const float* __restrict__ X, const float* __restrict__ W,
       const float* __restrict__ bin) {
    __shared__ float As[32 * 128];   // [k][row]
    __shared__ float Bs[32 * 128];   // [k][col]

    const int t  = threadIdx.x;
    const int tx = t & 15;
    const int ty = t >> 4;
    const int row0 = blockIdx.x * 128;

    const float4* X4 = FUSE ? reinterpret_cast<const float4*>(g_bufB)
                            : reinterpret_cast<const float4*>(X);
    const float4* W4 = reinterpret_cast<const float4*>(W);

    float acc[8][8];
    #pragma unroll
    for (int i = 0; i < 8; i++)
        #pragma unroll
        for (int j = 0; j < 8; j++) acc[i][j] = 0.0f;

    for (int k0 = 0; k0 < 128; k0 += 32) {
        #pragma unroll
        for (int i = 0; i < 4; i++) {
            int id = t + i * 256;
            int r  = id & 127;
            int q  = id >> 7;
            int grow = row0 + r;
            float4 v = make_float4(0.f, 0.f, 0.f, 0.f);
            if (grow < NN) {
                v = X4[grow * 32 + (k0 >> 2) + q];
                if (FUSE) {
                    float dv = g_dinv[grow];
                    int kk = k0 + q * 4;
                    v.x = fmaxf(fmaf(dv, v.x, bin[kk + 0]), 0.f);
                    v.y = fmaxf(fmaf(dv, v.y, bin[kk + 1]), 0.f);
                    v.z = fmaxf(fmaf(dv, v.z, bin[kk + 2]), 0.f);
                    v.w = fmaxf(fmaf(dv, v.w, bin[kk + 3]), 0.f);
                }
            }
            As[(q * 4 + 0) * 128 + r] = v.x;
            As[(q * 4 + 1) * 128 + r] = v.y;
            As[(q * 4 + 2) * 128 + r] = v.z;
            As[(q * 4 + 3) * 128 + r] = v.w;
        }
        #pragma unroll
        for (int i = 0; i < 4; i++) {
            int id = t + i * 256;
            int kr = id >> 5;
            int qc = id & 31;
            reinterpret_cast<float4*>(Bs)[kr * 32 + qc] = W4[(k0 + kr) * 32 + qc];
        }
        __syncthreads();

        #pragma unroll 4
        for (int k = 0; k < 32; k++) {
            float4 a0 = reinterpret_cast<float4*>(As)[k * 32 + ty * 2];
            float4 a1 = reinterpret_cast<float4*>(As)[k * 32 + ty * 2 + 1];
            float4 b0 = reinterpret_cast<float4*>(Bs)[k * 32 + tx * 2];
            float4 b1 = reinterpret_cast<float4*>(Bs)[k * 32 + tx * 2 + 1];
            float a[8] = {a0.x, a0.y, a0.z, a0.w, a1.x, a1.y, a1.z, a1.w};
            float b[8] = {b0.x, b0.y, b0.z, b0.w, b1.x, b1.y, b1.z, b1.w};
            #pragma unroll
            for (int i = 0; i < 8; i++)
                #pragma unroll
                for (int j = 0; j < 8; j++)
                    acc[i][j] = fmaf(a[i], b[j], acc[i][j]);
        }
        __syncthreads();
    }

    const int c4 = tx * 2;
    #pragma unroll
    for (int i = 0; i < 8; i++) {
        int grow = row0 + ty * 8 + i;
        if (grow < NN) {
            float dv = g_dinv[grow];
            float4 v0 = make_float4(acc[i][0] * dv, acc[i][1] * dv,
                                    acc[i][2] * dv, acc[i][3] * dv);
            float4 v1 = make_float4(acc[i][4] * dv, acc[i][5] * dv,
                                    acc[i][6] * dv, acc[i][7] * dv);
            float4* oa = reinterpret_cast<float4*>(g_bufA) + grow * 32 + c4;
            oa[0] = v0; oa[1] = v1;
        }
    }
}

// ---------------------------------------------------------------------------
// CSR gather aggregation. One warp per dst node.
// acc = bufA[n] (self-loop) + sum_{s in csr[n]} bufA[s].
// POOL=false: store raw acc -> bufB (consumed by FUSE GEMM).
// POOL=true : r = relu(dinv[n]*acc + b2), vector-RED into pool[batch[n]].
template<bool POOL>
__global__ void __launch_bounds__(256)
k_aggr(const int* __restrict__ batch, const float* __restrict__ b2) {
    int w = (blockIdx.x * blockDim.x + threadIdx.x) >> 5;
    int lane = threadIdx.x & 31;
    if (w >= NN) return;
    const int n = w;

    const float4* src4 = reinterpret_cast<const float4*>(g_bufA);
    float4 acc = src4[n * 32 + lane];        // self-loop message
    int beg = g_rowptr[n];
    int end = g_rowptr[n + 1];

    for (int base = beg; base < end; base += 32) {
        int idx = base + lane;
        int s_l = (idx < end) ? g_csr[idx] : 0;
        int cnt = min(32, end - base);
        for (int j = 0; j < cnt; j++) {
            int s = __shfl_sync(0xffffffffu, s_l, j);
            float4 v = src4[s * 32 + lane];
            acc.x += v.x; acc.y += v.y; acc.z += v.z; acc.w += v.w;
        }
    }

    if (!POOL) {
        reinterpret_cast<float4*>(g_bufB)[n * 32 + lane] = acc;
    } else {
        float dv = g_dinv[n];
        float4 bb = reinterpret_cast<const float4*>(b2)[lane];
        float4 r;
        r.x = fmaxf(fmaf(dv, acc.x, bb.x), 0.f);
        r.y = fmaxf(fmaf(dv, acc.y, bb.y), 0.f);
        r.z = fmaxf(fmaf(dv, acc.z, bb.z), 0.f);
        r.w = fmaxf(fmaf(dv, acc.w, bb.w), 0.f);
        int g = batch[n];
        red_add_v4(g_pool + g * D + lane * 4, r);
    }
}

// ---------------------------------------------------------------------------
// Head: out[g] = pool[g] @ Wl + bl   (512 x 64, K=128)
__global__ void k_final(const float* __restrict__ Wl,
                        const float* __restrict__ bl,
                        float* __restrict__ out) {
    __shared__ float p[D];
    int g = blockIdx.x;
    int o = threadIdx.x;
    p[o]      = g_pool[g * D + o];
    p[o + 64] = g_pool[g * D + o + 64];
    __syncthreads();
    float acc = bl[o];
    #pragma unroll 8
    for (int c = 0; c < D; c++)
        acc = fmaf(p[c], Wl[c * OD + o], acc);
    out[g * OD + o] = acc;
}

// ---------------------------------------------------------------------------
extern "C" void kernel_launch(void* const* d_in, const int* in_sizes, int n_in,
                              void* d_out, int out_size) {
    const float* x     = (const float*)d_in[0];
    const int*   ei    = (const int*)d_in[1];      // int32 (JAX x64 disabled)
    const int*   batch = (const int*)d_in[2];
    const float* W1    = (const float*)d_in[3];
    const float* b1    = (const float*)d_in[4];
    const float* W2    = (const float*)d_in[5];
    const float* b2    = (const float*)d_in[6];
    const float* Wl    = (const float*)d_in[7];
    const float* bl    = (const float*)d_in[8];
    float* out = (float*)d_out;

    // CSR build + norms.  NB: k_init must cover max(NN, NG*D) threads!
    k_init <<<(NN + 255) / 256, 256>>>();
    k_count<<<(EE + 255) / 256, 256>>>(ei);
    k_scan1<<<NBLK, SCAN_BLK>>>();
    k_scan2<<<1, 256>>>();
    k_scan3<<<NBLK, SCAN_BLK>>>();
    k_dinv <<<(NN + 255) / 256, 256>>>();
    k_fill <<<(EE + 255) / 256, 256>>>(ei);

    // Layer 1
    k_gemm<false><<<(NN + 127) / 128, 256>>>(x, W1, nullptr);
    k_aggr<false><<<(NN * 32 + 255) / 256, 256>>>(nullptr, nullptr);

    // Layer 2 (bias1+relu+dinv fused into GEMM A-load; pool fused into aggr)
    k_gemm<true><<<(NN + 127) / 128, 256>>>(nullptr, W2, b1);
    k_aggr<true><<<(NN * 32 + 255) / 256, 256>>>(batch, b2);

    k_final<<<NG, OD>>>(Wl, bl, out);
}

// round 8
// speedup vs baseline: 2.3248x; 1.3114x over previous
#include <cuda_runtime.h>
#include <cuda_bf16.h>
#include <cstdint>

#define NN 100000
#define EE 1600000
#define D  128
#define OD 64
#define NG 512
#define SCAN_BLK 512
#define NBLK ((NN + SCAN_BLK - 1) / SCAN_BLK)   // 196

// Scratch (device globals: allocation-free)
__device__ __align__(16) float g_bufA[NN * D];   // h_hat messages
__device__ __align__(16) float g_bufB[NN * D];   // aggregated raw sums
__device__ float g_dinv[NN];
__device__ __align__(16) float g_pool[NG * D];
__device__ int   g_cnt[NN];
__device__ int   g_pos[NN];
__device__ int   g_rowptr[NN + 1];
__device__ int   g_blksum[256];
__device__ int   g_csr[EE];
// Pre-transposed, bf16-split weights: [n*128 + k]
__device__ __align__(16) __nv_bfloat16 g_W1hi[D * D];
__device__ __align__(16) __nv_bfloat16 g_W1lo[D * D];
__device__ __align__(16) __nv_bfloat16 g_W2hi[D * D];
__device__ __align__(16) __nv_bfloat16 g_W2lo[D * D];

__device__ __forceinline__ void red_add_v4(float* addr, float4 v) {
    asm volatile("red.global.add.v4.f32 [%0], {%1,%2,%3,%4};"
                 :: "l"(__cvta_generic_to_global(addr)),
                    "f"(v.x), "f"(v.y), "f"(v.z), "f"(v.w)
                 : "memory");
}

// ---------------------------------------------------------------------------
__global__ void k_init() {
    int i = blockIdx.x * blockDim.x + threadIdx.x;
    if (i < NN) { g_cnt[i] = 0; g_pos[i] = 0; }
    if (i < NG * D) g_pool[i] = 0.0f;
}

__global__ void k_count(const int* __restrict__ ei) {
    int i = blockIdx.x * blockDim.x + threadIdx.x;
    if (i < EE) atomicAdd(&g_cnt[ei[EE + i]], 1);
}

__global__ void k_scan1() {
    __shared__ int s[SCAN_BLK];
    int gid = blockIdx.x * SCAN_BLK + threadIdx.x;
    int v = (gid < NN) ? g_cnt[gid] : 0;
    s[threadIdx.x] = v;
    __syncthreads();
    #pragma unroll
    for (int off = 1; off < SCAN_BLK; off <<= 1) {
        int t = (threadIdx.x >= off) ? s[threadIdx.x - off] : 0;
        __syncthreads();
        s[threadIdx.x] += t;
        __syncthreads();
    }
    if (gid < NN) g_rowptr[gid + 1] = s[threadIdx.x];
    if (threadIdx.x == SCAN_BLK - 1) g_blksum[blockIdx.x] = s[threadIdx.x];
    if (gid == 0) g_rowptr[0] = 0;
}

__global__ void k_scan2() {
    __shared__ int s[256];
    int v = (threadIdx.x < NBLK) ? g_blksum[threadIdx.x] : 0;
    s[threadIdx.x] = v;
    __syncthreads();
    #pragma unroll
    for (int off = 1; off < 256; off <<= 1) {
        int t = (threadIdx.x >= off) ? s[threadIdx.x - off] : 0;
        __syncthreads();
        s[threadIdx.x] += t;
        __syncthreads();
    }
    if (threadIdx.x < NBLK) g_blksum[threadIdx.x] = s[threadIdx.x] - v;
}

__global__ void k_scan3() {
    int gid = blockIdx.x * SCAN_BLK + threadIdx.x;
    if (gid < NN) g_rowptr[gid + 1] += g_blksum[blockIdx.x];
}

__global__ void k_dinv() {
    int i = blockIdx.x * blockDim.x + threadIdx.x;
    if (i < NN) g_dinv[i] = rsqrtf((float)(g_cnt[i] + 1));
}

__global__ void k_fill(const int* __restrict__ ei) {
    int i = blockIdx.x * blockDim.x + threadIdx.x;
    if (i < EE) {
        int s = ei[i];
        int d = ei[EE + i];
        int slot = g_rowptr[d] + atomicAdd(&g_pos[d], 1);
        g_csr[slot] = s;
    }
}

// Transpose + bf16-split weights: Wt[n][k] = W[k][n] as (hi, lo)
__global__ void k_prepw(const float* __restrict__ W1, const float* __restrict__ W2) {
    int id = blockIdx.x * blockDim.x + threadIdx.x;   // 0..32767
    int w = id >> 14;
    int r = id & 16383;
    int k = r >> 7, n = r & 127;
    float v = (w ? W2 : W1)[k * D + n];
    __nv_bfloat16 hi = __float2bfloat16_rn(v);
    __nv_bfloat16 lo = __float2bfloat16_rn(v - __bfloat162float(hi));
    (w ? g_W2hi : g_W1hi)[n * D + k] = hi;
    (w ? g_W2lo : g_W1lo)[n * D + k] = lo;
}

// ---------------------------------------------------------------------------
// Split-bf16 tensor GEMM via mma.sync: bufA = dinv[row] * (in @ W).
// 128x128 tile per CTA, K=128 in 2 chunks of 64, double-buffered smem.
// 8 warps: warp_m = wid&3 (32 rows), warp_n = wid>>2 (64 cols).
// LAYER selects weights (device globals referenced IN device code).

#define SWZ(x) ((x) ^ (((x) >> 3) & 0x70))
#define CHUNK_BYTES 65536
#define AHI_OFF(b) ((b) * CHUNK_BYTES + 0)
#define ALO_OFF(b) ((b) * CHUNK_BYTES + 16384)
#define BHI_OFF(b) ((b) * CHUNK_BYTES + 32768)
#define BLO_OFF(b) ((b) * CHUNK_BYTES + 49152)
#define GEMM_SMEM  (2 * CHUNK_BYTES)

__device__ __forceinline__ void ldm4(uint32_t* r, uint32_t addr) {
    asm volatile("ldmatrix.sync.aligned.m8n8.x4.shared.b16 {%0,%1,%2,%3}, [%4];"
                 : "=r"(r[0]), "=r"(r[1]), "=r"(r[2]), "=r"(r[3]) : "r"(addr));
}

__device__ __forceinline__ void mma16816(float* c, const uint32_t* a, const uint32_t* b) {
    asm("mma.sync.aligned.m16n8k16.row.col.f32.bf16.bf16.f32 "
        "{%0,%1,%2,%3}, {%4,%5,%6,%7}, {%8,%9}, {%0,%1,%2,%3};"
        : "+f"(c[0]), "+f"(c[1]), "+f"(c[2]), "+f"(c[3])
        : "r"(a[0]), "r"(a[1]), "r"(a[2]), "r"(a[3]), "r"(b[0]), "r"(b[1]));
}

__device__ __forceinline__ uint32_t pack_bf2(float a, float b) {
    __nv_bfloat162 t = __floats2bfloat162_rn(a, b);
    return *reinterpret_cast<uint32_t*>(&t);
}

template<int LAYER>   // 1: in=X, W1;  2: in=relu(dinv*bufB+bin), W2
__global__ void __launch_bounds__(256, 1)
k_gemm_mma(const float* __restrict__ X, const float* __restrict__ bin) {
    extern __shared__ char smem[];
    uint32_t sb;
    { uint64_t tmp; asm("cvta.to.shared.u64 %0, %1;" : "=l"(tmp) : "l"(smem)); sb = (uint32_t)tmp; }

    constexpr bool FUSE = (LAYER == 2);
    const int t = threadIdx.x;
    const int wid = t >> 5;
    const int lid = t & 31;
    const int row0 = blockIdx.x * 128;
    const int warp_m = wid & 3;
    const int warp_n = wid >> 2;

    const float4* X4 = FUSE ? reinterpret_cast<const float4*>(g_bufB)
                            : reinterpret_cast<const float4*>(X);
    const uint4* WH4 = reinterpret_cast<const uint4*>(LAYER == 1 ? g_W1hi : g_W2hi);
    const uint4* WL4 = reinterpret_cast<const uint4*>(LAYER == 1 ? g_W1lo : g_W2lo);
    const float4* B4 = reinterpret_cast<const float4*>(bin);

    float acc[2][8][4];
    #pragma unroll
    for (int i = 0; i < 2; i++)
        #pragma unroll
        for (int j = 0; j < 8; j++)
            #pragma unroll
            for (int q = 0; q < 4; q++) acc[i][j][q] = 0.0f;

    for (int c = 0; c < 2; c++) {
        // ---- stage chunk c (k = c*64 .. +63) into buffer c ----
        // A: 128 rows x 64 k fp32 -> split bf16. 4 threads/row, 2 halves.
        #pragma unroll
        for (int h = 0; h < 2; h++) {
            int r  = h * 64 + (t >> 2);
            int kq = t & 3;                     // 16 floats each
            int grow = row0 + r;
            float vv[16];
            if (grow < NN) {
                #pragma unroll
                for (int i = 0; i < 4; i++) {
                    float4 v = X4[grow * 32 + c * 16 + kq * 4 + i];
                    if (FUSE) {
                        float dv = g_dinv[grow];
                        float4 bb = B4[c * 16 + kq * 4 + i];
                        v.x = fmaxf(fmaf(dv, v.x, bb.x), 0.f);
                        v.y = fmaxf(fmaf(dv, v.y, bb.y), 0.f);
                        v.z = fmaxf(fmaf(dv, v.z, bb.z), 0.f);
                        v.w = fmaxf(fmaf(dv, v.w, bb.w), 0.f);
                    }
                    vv[i * 4 + 0] = v.x; vv[i * 4 + 1] = v.y;
                    vv[i * 4 + 2] = v.z; vv[i * 4 + 3] = v.w;
                }
            } else {
                #pragma unroll
                for (int i = 0; i < 16; i++) vv[i] = 0.f;
            }
            uint32_t hi[8], lo[8];
            #pragma unroll
            for (int i = 0; i < 8; i++) {
                float a = vv[2 * i], b = vv[2 * i + 1];
                __nv_bfloat16 ha = __float2bfloat16_rn(a);
                __nv_bfloat16 hb = __float2bfloat16_rn(b);
                hi[i] = pack_bf2(a, b);
                lo[i] = pack_bf2(a - __bfloat162float(ha), b - __bfloat162float(hb));
            }
            uint32_t base = (uint32_t)(r * 128 + kq * 32);
            *reinterpret_cast<uint4*>(smem + AHI_OFF(c) + SWZ(base)) =
                make_uint4(hi[0], hi[1], hi[2], hi[3]);
            *reinterpret_cast<uint4*>(smem + AHI_OFF(c) + SWZ(base + 16)) =
                make_uint4(hi[4], hi[5], hi[6], hi[7]);
            *reinterpret_cast<uint4*>(smem + ALO_OFF(c) + SWZ(base)) =
                make_uint4(lo[0], lo[1], lo[2], lo[3]);
            *reinterpret_cast<uint4*>(smem + ALO_OFF(c) + SWZ(base + 16)) =
                make_uint4(lo[4], lo[5], lo[6], lo[7]);
        }
        // B: 128 n-rows x 64 k bf16 (pre-split). 2 threads/row.
        {
            int n  = t >> 1;
            int kq = t & 1;                     // 32 bf16 each
            #pragma unroll
            for (int i = 0; i < 4; i++) {
                uint4 hv = WH4[n * 16 + c * 8 + kq * 4 + i];
                uint4 lv = WL4[n * 16 + c * 8 + kq * 4 + i];
                uint32_t off = (uint32_t)(n * 128 + kq * 64 + i * 16);
                *reinterpret_cast<uint4*>(smem + BHI_OFF(c) + SWZ(off)) = hv;
                *reinterpret_cast<uint4*>(smem + BLO_OFF(c) + SWZ(off)) = lv;
            }
        }
        __syncthreads();

        // ---- compute chunk c: 4 k-steps of 16 ----
        #pragma unroll
        for (int ks = 0; ks < 4; ks++) {
            uint32_t ah[2][4], al[2][4];
            #pragma unroll
            for (int mt = 0; mt < 2; mt++) {
                uint32_t off = SWZ((uint32_t)((warp_m * 32 + mt * 16 + (lid & 15)) * 128
                                              + ks * 32 + (lid >> 4) * 16));
                ldm4(ah[mt], sb + AHI_OFF(c) + off);
                ldm4(al[mt], sb + ALO_OFF(c) + off);
            }
            uint32_t bh[8][2], bl[8][2];
            #pragma unroll
            for (int ntp = 0; ntp < 4; ntp++) {
                uint32_t nrow = (lid & 7) + ((lid >> 4) & 1) * 8;
                uint32_t kb = ((lid >> 3) & 1) * 16;
                uint32_t off = SWZ((uint32_t)((warp_n * 64 + ntp * 16 + nrow) * 128
                                              + ks * 32 + kb));
                uint32_t r[4];
                ldm4(r, sb + BHI_OFF(c) + off);
                bh[2 * ntp][0] = r[0]; bh[2 * ntp][1] = r[1];
                bh[2 * ntp + 1][0] = r[2]; bh[2 * ntp + 1][1] = r[3];
                ldm4(r, sb + BLO_OFF(c) + off);
                bl[2 * ntp][0] = r[0]; bl[2 * ntp][1] = r[1];
                bl[2 * ntp + 1][0] = r[2]; bl[2 * ntp + 1][1] = r[3];
            }
            #pragma unroll
            for (int mt = 0; mt < 2; mt++)
                #pragma unroll
                for (int nt = 0; nt < 8; nt++) {
                    mma16816(acc[mt][nt], ah[mt], bh[nt]);
                    mma16816(acc[mt][nt], ah[mt], bl[nt]);
                    mma16816(acc[mt][nt], al[mt], bh[nt]);
                }
        }
    }

    // ---- epilogue: scale by dinv[row], store to bufA ----
    const int g = lid >> 2, tig = lid & 3;
    #pragma unroll
    for (int mt = 0; mt < 2; mt++) {
        int m0 = row0 + warp_m * 32 + mt * 16 + g;
        int m8 = m0 + 8;
        float dv0 = (m0 < NN) ? g_dinv[m0] : 0.f;
        float dv8 = (m8 < NN) ? g_dinv[m8] : 0.f;
        #pragma unroll
        for (int nt = 0; nt < 8; nt++) {
            int col = warp_n * 64 + nt * 8 + tig * 2;
            if (m0 < NN) {
                float2 v = make_float2(acc[mt][nt][0] * dv0, acc[mt][nt][1] * dv0);
                *reinterpret_cast<float2*>(g_bufA + m0 * D + col) = v;
            }
            if (m8 < NN) {
                float2 v = make_float2(acc[mt][nt][2] * dv8, acc[mt][nt][3] * dv8);
                *reinterpret_cast<float2*>(g_bufA + m8 * D + col) = v;
            }
        }
    }
}

// ---------------------------------------------------------------------------
// CSR gather aggregation. One warp per dst node.
template<bool POOL>
__global__ void __launch_bounds__(256)
k_aggr(const int* __restrict__ batch, const float* __restrict__ b2) {
    int w = (blockIdx.x * blockDim.x + threadIdx.x) >> 5;
    int lane = threadIdx.x & 31;
    if (w >= NN) return;
    const int n = w;

    const float4* src4 = reinterpret_cast<const float4*>(g_bufA);
    float4 acc = src4[n * 32 + lane];
    int beg = g_rowptr[n];
    int end = g_rowptr[n + 1];

    for (int base = beg; base < end; base += 32) {
        int idx = base + lane;
        int s_l = (idx < end) ? g_csr[idx] : 0;
        int cnt = min(32, end - base);
        for (int j = 0; j < cnt; j++) {
            int s = __shfl_sync(0xffffffffu, s_l, j);
            float4 v = src4[s * 32 + lane];
            acc.x += v.x; acc.y += v.y; acc.z += v.z; acc.w += v.w;
        }
    }

    if (!POOL) {
        reinterpret_cast<float4*>(g_bufB)[n * 32 + lane] = acc;
    } else {
        float dv = g_dinv[n];
        float4 bb = reinterpret_cast<const float4*>(b2)[lane];
        float4 r;
        r.x = fmaxf(fmaf(dv, acc.x, bb.x), 0.f);
        r.y = fmaxf(fmaf(dv, acc.y, bb.y), 0.f);
        r.z = fmaxf(fmaf(dv, acc.z, bb.z), 0.f);
        r.w = fmaxf(fmaf(dv, acc.w, bb.w), 0.f);
        int g = batch[n];
        red_add_v4(g_pool + g * D + lane * 4, r);
    }
}

// ---------------------------------------------------------------------------
__global__ void k_final(const float* __restrict__ Wl,
                        const float* __restrict__ bl,
                        float* __restrict__ out) {
    __shared__ float p[D];
    int g = blockIdx.x;
    int o = threadIdx.x;
    p[o]      = g_pool[g * D + o];
    p[o + 64] = g_pool[g * D + o + 64];
    __syncthreads();
    float acc = bl[o];
    #pragma unroll 8
    for (int c = 0; c < D; c++)
        acc = fmaf(p[c], Wl[c * OD + o], acc);
    out[g * OD + o] = acc;
}

// ---------------------------------------------------------------------------
extern "C" void kernel_launch(void* const* d_in, const int* in_sizes, int n_in,
                              void* d_out, int out_size) {
    const float* x     = (const float*)d_in[0];
    const int*   ei    = (const int*)d_in[1];      // int32 (JAX x64 disabled)
    const int*   batch = (const int*)d_in[2];
    const float* W1    = (const float*)d_in[3];
    const float* b1    = (const float*)d_in[4];
    const float* W2    = (const float*)d_in[5];
    const float* b2    = (const float*)d_in[6];
    const float* Wl    = (const float*)d_in[7];
    const float* bl    = (const float*)d_in[8];
    float* out = (float*)d_out;

    cudaFuncSetAttribute(k_gemm_mma<1>,
                         cudaFuncAttributeMaxDynamicSharedMemorySize, GEMM_SMEM);
    cudaFuncSetAttribute(k_gemm_mma<2>,
                         cudaFuncAttributeMaxDynamicSharedMemorySize, GEMM_SMEM);

    // CSR build + norms + weight prep
    k_init <<<(NN + 255) / 256, 256>>>();
    k_count<<<(EE + 255) / 256, 256>>>(ei);
    k_prepw<<<128, 256>>>(W1, W2);
    k_scan1<<<NBLK, SCAN_BLK>>>();
    k_scan2<<<1, 256>>>();
    k_scan3<<<NBLK, SCAN_BLK>>>();
    k_dinv <<<(NN + 255) / 256, 256>>>();
    k_fill <<<(EE + 255) / 256, 256>>>(ei);

    // Layer 1
    k_gemm_mma<1><<<(NN + 127) / 128, 256, GEMM_SMEM>>>(x, nullptr);
    k_aggr<false><<<(NN * 32 + 255) / 256, 256>>>(nullptr, nullptr);

    // Layer 2
    k_gemm_mma<2><<<(NN + 127) / 128, 256, GEMM_SMEM>>>(nullptr, b1);
    k_aggr<true><<<(NN * 32 + 255) / 256, 256>>>(batch, b2);

    k_final<<<NG, OD>>>(Wl, bl, out);
}

// round 9
// speedup vs baseline: 2.6197x; 1.1269x over previous
#include <cuda_runtime.h>
#include <cuda_bf16.h>
#include <cuda_fp16.h>
#include <cstdint>

#define NN 100000
#define EE 1600000
#define D  128
#define OD 64
#define NG 512
#define SCAN_BLK 512
#define NBLK ((NN + SCAN_BLK - 1) / SCAN_BLK)   // 196

// Scratch (device globals: allocation-free)
__device__ __align__(16) __half g_bufA[NN * D];  // h_hat messages (fp16)
__device__ __align__(16) float  g_bufB[NN * D];  // aggregated raw sums (fp32)
__device__ float g_dinv[NN];
__device__ __align__(16) float g_pool[NG * D];
__device__ int   g_cnt[NN];
__device__ int   g_pos[NN];          // exclusive rowptr copy -> fill cursors
__device__ int   g_rowptr[NN + 1];
__device__ int   g_blksum[256];
__device__ int   g_csr[EE];
// Pre-transposed, bf16-split weights: [n*128 + k]
__device__ __align__(16) __nv_bfloat16 g_W1hi[D * D];
__device__ __align__(16) __nv_bfloat16 g_W1lo[D * D];
__device__ __align__(16) __nv_bfloat16 g_W2hi[D * D];
__device__ __align__(16) __nv_bfloat16 g_W2lo[D * D];

__device__ __forceinline__ void red_add_v4(float* addr, float4 v) {
    asm volatile("red.global.add.v4.f32 [%0], {%1,%2,%3,%4};"
                 :: "l"(__cvta_generic_to_global(addr)),
                    "f"(v.x), "f"(v.y), "f"(v.z), "f"(v.w)
                 : "memory");
}

// ---------------------------------------------------------------------------
__global__ void k_init() {
    int i = blockIdx.x * blockDim.x + threadIdx.x;
    if (i < NN) g_cnt[i] = 0;
    if (i < NG * D) g_pool[i] = 0.0f;
}

__global__ void k_count(const int* __restrict__ ei) {
    int i = blockIdx.x * blockDim.x + threadIdx.x;
    if (i < EE) atomicAdd(&g_cnt[ei[EE + i]], 1);
}

__global__ void k_scan1() {
    __shared__ int s[SCAN_BLK];
    int gid = blockIdx.x * SCAN_BLK + threadIdx.x;
    int v = (gid < NN) ? g_cnt[gid] : 0;
    s[threadIdx.x] = v;
    __syncthreads();
    #pragma unroll
    for (int off = 1; off < SCAN_BLK; off <<= 1) {
        int t = (threadIdx.x >= off) ? s[threadIdx.x - off] : 0;
        __syncthreads();
        s[threadIdx.x] += t;
        __syncthreads();
    }
    if (gid < NN) g_rowptr[gid + 1] = s[threadIdx.x];
    if (threadIdx.x == SCAN_BLK - 1) g_blksum[blockIdx.x] = s[threadIdx.x];
    if (gid == 0) g_rowptr[0] = 0;
}

__global__ void k_scan2() {
    __shared__ int s[256];
    int v = (threadIdx.x < NBLK) ? g_blksum[threadIdx.x] : 0;
    s[threadIdx.x] = v;
    __syncthreads();
    #pragma unroll
    for (int off = 1; off < 256; off <<= 1) {
        int t = (threadIdx.x >= off) ? s[threadIdx.x - off] : 0;
        __syncthreads();
        s[threadIdx.x] += t;
        __syncthreads();
    }
    if (threadIdx.x < NBLK) g_blksum[threadIdx.x] = s[threadIdx.x] - v;
}

// scan3: finalize rowptr, seed fill cursors (exclusive prefix), compute dinv.
__global__ void k_scan3() {
    int gid = blockIdx.x * SCAN_BLK + threadIdx.x;
    if (gid < NN) {
        int incl = g_rowptr[gid + 1] + g_blksum[blockIdx.x];
        g_rowptr[gid + 1] = incl;
        int cnt = g_cnt[gid];
        g_pos[gid] = incl - cnt;                 // exclusive prefix
        g_dinv[gid] = rsqrtf((float)(cnt + 1));  // +1 self-loop
    }
}

__global__ void k_fill(const int* __restrict__ ei) {
    int i = blockIdx.x * blockDim.x + threadIdx.x;
    if (i < EE) {
        int s = ei[i];
        int d = ei[EE + i];
        g_csr[atomicAdd(&g_pos[d], 1)] = s;
    }
}

// Transpose + bf16-split weights: Wt[n][k] = W[k][n] as (hi, lo)
__global__ void k_prepw(const float* __restrict__ W1, const float* __restrict__ W2) {
    int id = blockIdx.x * blockDim.x + threadIdx.x;   // 0..32767
    int w = id >> 14;
    int r = id & 16383;
    int k = r >> 7, n = r & 127;
    float v = (w ? W2 : W1)[k * D + n];
    __nv_bfloat16 hi = __float2bfloat16_rn(v);
    __nv_bfloat16 lo = __float2bfloat16_rn(v - __bfloat162float(hi));
    (w ? g_W2hi : g_W1hi)[n * D + k] = hi;
    (w ? g_W2lo : g_W1lo)[n * D + k] = lo;
}

// ---------------------------------------------------------------------------
// Split-bf16 tensor GEMM via mma.sync: bufA(fp16) = dinv[row] * (in @ W).
// 128x128 tile per CTA, K=128 in 2 chunks of 64, 8 warps.

#define SWZ(x) ((x) ^ (((x) >> 3) & 0x70))
#define CHUNK_BYTES 65536
#define AHI_OFF(b) ((b) * CHUNK_BYTES + 0)
#define ALO_OFF(b) ((b) * CHUNK_BYTES + 16384)
#define BHI_OFF(b) ((b) * CHUNK_BYTES + 32768)
#define BLO_OFF(b) ((b) * CHUNK_BYTES + 49152)
#define GEMM_SMEM  (2 * CHUNK_BYTES)

__device__ __forceinline__ void ldm4(uint32_t* r, uint32_t addr) {
    asm volatile("ldmatrix.sync.aligned.m8n8.x4.shared.b16 {%0,%1,%2,%3}, [%4];"
                 : "=r"(r[0]), "=r"(r[1]), "=r"(r[2]), "=r"(r[3]) : "r"(addr));
}

__device__ __forceinline__ void mma16816(float* c, const uint32_t* a, const uint32_t* b) {
    asm("mma.sync.aligned.m16n8k16.row.col.f32.bf16.bf16.f32 "
        "{%0,%1,%2,%3}, {%4,%5,%6,%7}, {%8,%9}, {%0,%1,%2,%3};"
        : "+f"(c[0]), "+f"(c[1]), "+f"(c[2]), "+f"(c[3])
        : "r"(a[0]), "r"(a[1]), "r"(a[2]), "r"(a[3]), "r"(b[0]), "r"(b[1]));
}

__device__ __forceinline__ uint32_t pack_bf2(float a, float b) {
    __nv_bfloat162 t = __floats2bfloat162_rn(a, b);
    return *reinterpret_cast<uint32_t*>(&t);
}

template<int LAYER>   // 1: in=X, W1;  2: in=relu(dinv*bufB+bin), W2
__global__ void __launch_bounds__(256, 1)
k_gemm_mma(const float* __restrict__ X, const float* __restrict__ bin) {
    extern __shared__ char smem[];
    uint32_t sb;
    { uint64_t tmp; asm("cvta.to.shared.u64 %0, %1;" : "=l"(tmp) : "l"(smem)); sb = (uint32_t)tmp; }

    constexpr bool FUSE = (LAYER == 2);
    const int t = threadIdx.x;
    const int wid = t >> 5;
    const int lid = t & 31;
    const int row0 = blockIdx.x * 128;
    const int warp_m = wid & 3;
    const int warp_n = wid >> 2;

    const float4* X4 = FUSE ? reinterpret_cast<const float4*>(g_bufB)
                            : reinterpret_cast<const float4*>(X);
    const uint4* WH4 = reinterpret_cast<const uint4*>(LAYER == 1 ? g_W1hi : g_W2hi);
    const uint4* WL4 = reinterpret_cast<const uint4*>(LAYER == 1 ? g_W1lo : g_W2lo);
    const float4* B4 = reinterpret_cast<const float4*>(bin);

    float acc[2][8][4];
    #pragma unroll
    for (int i = 0; i < 2; i++)
        #pragma unroll
        for (int j = 0; j < 8; j++)
            #pragma unroll
            for (int q = 0; q < 4; q++) acc[i][j][q] = 0.0f;

    for (int c = 0; c < 2; c++) {
        // ---- stage chunk c (k = c*64 .. +63) ----
        #pragma unroll
        for (int h = 0; h < 2; h++) {
            int r  = h * 64 + (t >> 2);
            int kq = t & 3;                     // 16 floats each
            int grow = row0 + r;
            float vv[16];
            if (grow < NN) {
                #pragma unroll
                for (int i = 0; i < 4; i++) {
                    float4 v = X4[grow * 32 + c * 16 + kq * 4 + i];
                    if (FUSE) {
                        float dv = g_dinv[grow];
                        float4 bb = B4[c * 16 + kq * 4 + i];
                        v.x = fmaxf(fmaf(dv, v.x, bb.x), 0.f);
                        v.y = fmaxf(fmaf(dv, v.y, bb.y), 0.f);
                        v.z = fmaxf(fmaf(dv, v.z, bb.z), 0.f);
                        v.w = fmaxf(fmaf(dv, v.w, bb.w), 0.f);
                    }
                    vv[i * 4 + 0] = v.x; vv[i * 4 + 1] = v.y;
                    vv[i * 4 + 2] = v.z; vv[i * 4 + 3] = v.w;
                }
            } else {
                #pragma unroll
                for (int i = 0; i < 16; i++) vv[i] = 0.f;
            }
            uint32_t hi[8], lo[8];
            #pragma unroll
            for (int i = 0; i < 8; i++) {
                float a = vv[2 * i], b = vv[2 * i + 1];
                __nv_bfloat16 ha = __float2bfloat16_rn(a);
                __nv_bfloat16 hb = __float2bfloat16_rn(b);
                hi[i] = pack_bf2(a, b);
                lo[i] = pack_bf2(a - __bfloat162float(ha), b - __bfloat162float(hb));
            }
            uint32_t base = (uint32_t)(r * 128 + kq * 32);
            *reinterpret_cast<uint4*>(smem + AHI_OFF(c) + SWZ(base)) =
                make_uint4(hi[0], hi[1], hi[2], hi[3]);
            *reinterpret_cast<uint4*>(smem + AHI_OFF(c) + SWZ(base + 16)) =
                make_uint4(hi[4], hi[5], hi[6], hi[7]);
            *reinterpret_cast<uint4*>(smem + ALO_OFF(c) + SWZ(base)) =
                make_uint4(lo[0], lo[1], lo[2], lo[3]);
            *reinterpret_cast<uint4*>(smem + ALO_OFF(c) + SWZ(base + 16)) =
                make_uint4(lo[4], lo[5], lo[6], lo[7]);
        }
        // B: 128 n-rows x 64 k bf16 (pre-split). 2 threads/row.
        {
            int n  = t >> 1;
            int kq = t & 1;
            #pragma unroll
            for (int i = 0; i < 4; i++) {
                uint4 hv = WH4[n * 16 + c * 8 + kq * 4 + i];
                uint4 lv = WL4[n * 16 + c * 8 + kq * 4 + i];
                uint32_t off = (uint32_t)(n * 128 + kq * 64 + i * 16);
                *reinterpret_cast<uint4*>(smem + BHI_OFF(c) + SWZ(off)) = hv;
                *reinterpret_cast<uint4*>(smem + BLO_OFF(c) + SWZ(off)) = lv;
            }
        }
        __syncthreads();

        // ---- compute chunk c: 4 k-steps of 16 ----
        #pragma unroll
        for (int ks = 0; ks < 4; ks++) {
            uint32_t ah[2][4], al[2][4];
            #pragma unroll
            for (int mt = 0; mt < 2; mt++) {
                uint32_t off = SWZ((uint32_t)((warp_m * 32 + mt * 16 + (lid & 15)) * 128
                                              + ks * 32 + (lid >> 4) * 16));
                ldm4(ah[mt], sb + AHI_OFF(c) + off);
                ldm4(al[mt], sb + ALO_OFF(c) + off);
            }
            uint32_t bh[8][2], bl[8][2];
            #pragma unroll
            for (int ntp = 0; ntp < 4; ntp++) {
                uint32_t nrow = (lid & 7) + ((lid >> 4) & 1) * 8;
                uint32_t kb = ((lid >> 3) & 1) * 16;
                uint32_t off = SWZ((uint32_t)((warp_n * 64 + ntp * 16 + nrow) * 128
                                              + ks * 32 + kb));
                uint32_t r[4];
                ldm4(r, sb + BHI_OFF(c) + off);
                bh[2 * ntp][0] = r[0]; bh[2 * ntp][1] = r[1];
                bh[2 * ntp + 1][0] = r[2]; bh[2 * ntp + 1][1] = r[3];
                ldm4(r, sb + BLO_OFF(c) + off);
                bl[2 * ntp][0] = r[0]; bl[2 * ntp][1] = r[1];
                bl[2 * ntp + 1][0] = r[2]; bl[2 * ntp + 1][1] = r[3];
            }
            #pragma unroll
            for (int mt = 0; mt < 2; mt++)
                #pragma unroll
                for (int nt = 0; nt < 8; nt++) {
                    mma16816(acc[mt][nt], ah[mt], bh[nt]);
                    mma16816(acc[mt][nt], ah[mt], bl[nt]);
                    mma16816(acc[mt][nt], al[mt], bh[nt]);
                }
        }
    }

    // ---- epilogue: scale by dinv[row], store fp16 to bufA ----
    const int g = lid >> 2, tig = lid & 3;
    #pragma unroll
    for (int mt = 0; mt < 2; mt++) {
        int m0 = row0 + warp_m * 32 + mt * 16 + g;
        int m8 = m0 + 8;
        float dv0 = (m0 < NN) ? g_dinv[m0] : 0.f;
        float dv8 = (m8 < NN) ? g_dinv[m8] : 0.f;
        #pragma unroll
        for (int nt = 0; nt < 8; nt++) {
            int col = warp_n * 64 + nt * 8 + tig * 2;
            if (m0 < NN) {
                float2 v = make_float2(acc[mt][nt][0] * dv0, acc[mt][nt][1] * dv0);
                *reinterpret_cast<__half2*>(g_bufA + m0 * D + col) = __float22half2_rn(v);
            }
            if (m8 < NN) {
                float2 v = make_float2(acc[mt][nt][2] * dv8, acc[mt][nt][3] * dv8);
                *reinterpret_cast<__half2*>(g_bufA + m8 * D + col) = __float22half2_rn(v);
            }
        }
    }
}

// ---------------------------------------------------------------------------
// CSR gather aggregation over fp16 messages. One warp per dst node.
// Lane owns dims [lane*4, lane*4+3] (one uint2 = 4 halves; row = 256B).
template<bool POOL>
__global__ void __launch_bounds__(256)
k_aggr(const int* __restrict__ batch, const float* __restrict__ b2) {
    int w = (blockIdx.x * blockDim.x + threadIdx.x) >> 5;
    int lane = threadIdx.x & 31;
    if (w >= NN) return;
    const int n = w;

    const uint2* src = reinterpret_cast<const uint2*>(g_bufA);  // 32 uint2 per row
    float acc0, acc1, acc2, acc3;
    {
        uint2 u = src[n * 32 + lane];
        float2 a = __half22float2(*reinterpret_cast<__half2*>(&u.x));
        float2 b = __half22float2(*reinterpret_cast<__half2*>(&u.y));
        acc0 = a.x; acc1 = a.y; acc2 = b.x; acc3 = b.y;
    }
    int beg = g_rowptr[n];
    int end = g_rowptr[n + 1];

    for (int base = beg; base < end; base += 32) {
        int idx = base + lane;
        int s_l = (idx < end) ? g_csr[idx] : 0;
        int cnt = min(32, end - base);
        for (int j = 0; j < cnt; j++) {
            int s = __shfl_sync(0xffffffffu, s_l, j);
            uint2 u = src[s * 32 + lane];
            float2 a = __half22float2(*reinterpret_cast<__half2*>(&u.x));
            float2 b = __half22float2(*reinterpret_cast<__half2*>(&u.y));
            acc0 += a.x; acc1 += a.y; acc2 += b.x; acc3 += b.y;
        }
    }

    if (!POOL) {
        reinterpret_cast<float4*>(g_bufB)[n * 32 + lane] =
            make_float4(acc0, acc1, acc2, acc3);
    } else {
        float dv = g_dinv[n];
        float4 bb = reinterpret_cast<const float4*>(b2)[lane];
        float4 r;
        r.x = fmaxf(fmaf(dv, acc0, bb.x), 0.f);
        r.y = fmaxf(fmaf(dv, acc1, bb.y), 0.f);
        r.z = fmaxf(fmaf(dv, acc2, bb.z), 0.f);
        r.w = fmaxf(fmaf(dv, acc3, bb.w), 0.f);
        int g = batch[n];
        red_add_v4(g_pool + g * D + lane * 4, r);
    }
}

// ---------------------------------------------------------------------------
__global__ void k_final(const float* __restrict__ Wl,
                        const float* __restrict__ bl,
                        float* __restrict__ out) {
    __shared__ float p[D];
    int g = blockIdx.x;
    int o = threadIdx.x;
    p[o]      = g_pool[g * D + o];
    p[o + 64] = g_pool[g * D + o + 64];
    __syncthreads();
    float acc = bl[o];
    #pragma unroll 8
    for (int c = 0; c < D; c++)
        acc = fmaf(p[c], Wl[c * OD + o], acc);
    out[g * OD + o] = acc;
}

// ---------------------------------------------------------------------------
extern "C" void kernel_launch(void* const* d_in, const int* in_sizes, int n_in,
                              void* d_out, int out_size) {
    const float* x     = (const float*)d_in[0];
    const int*   ei    = (const int*)d_in[1];      // int32 (JAX x64 disabled)
    const int*   batch = (const int*)d_in[2];
    const float* W1    = (const float*)d_in[3];
    const float* b1    = (const float*)d_in[4];
    const float* W2    = (const float*)d_in[5];
    const float* b2    = (const float*)d_in[6];
    const float* Wl    = (const float*)d_in[7];
    const float* bl    = (const float*)d_in[8];
    float* out = (float*)d_out;

    cudaFuncSetAttribute(k_gemm_mma<1>,
                         cudaFuncAttributeMaxDynamicSharedMemorySize, GEMM_SMEM);
    cudaFuncSetAttribute(k_gemm_mma<2>,
                         cudaFuncAttributeMaxDynamicSharedMemorySize, GEMM_SMEM);

    // CSR build + norms + weight prep
    k_init <<<(NN + 255) / 256, 256>>>();
    k_count<<<(EE + 255) / 256, 256>>>(ei);
    k_prepw<<<128, 256>>>(W1, W2);
    k_scan1<<<NBLK, SCAN_BLK>>>();
    k_scan2<<<1, 256>>>();
    k_scan3<<<NBLK, SCAN_BLK>>>();   // rowptr final + cursors + dinv
    k_fill <<<(EE + 255) / 256, 256>>>(ei);

    // Layer 1
    k_gemm_mma<1><<<(NN + 127) / 128, 256, GEMM_SMEM>>>(x, nullptr);
    k_aggr<false><<<(NN * 32 + 255) / 256, 256>>>(nullptr, nullptr);

    // Layer 2
    k_gemm_mma<2><<<(NN + 127) / 128, 256, GEMM_SMEM>>>(nullptr, b1);
    k_aggr<true><<<(NN * 32 + 255) / 256, 256>>>(batch, b2);

    k_final<<<NG, OD>>>(Wl, bl, out);
}

// round 10
// speedup vs baseline: 2.7392x; 1.0456x over previous
#include <cuda_runtime.h>
#include <cuda_bf16.h>
#include <cstdint>

#define NN 100000
#define EE 1600000
#define D  128
#define OD 64
#define NG 512
#define SCAN_BLK 512
#define NBLK ((NN + SCAN_BLK - 1) / SCAN_BLK)   // 196

// Scratch (device globals: allocation-free)
__device__ __align__(16) __nv_bfloat16 g_bufA[NN * D];  // messages (bf16)
__device__ __align__(16) __nv_bfloat16 g_Ahi[NN * D];   // GEMM A input hi
__device__ __align__(16) __nv_bfloat16 g_Alo[NN * D];   // GEMM A input lo
__device__ float g_dinv[NN];
__device__ __align__(16) float g_pool[NG * D];
__device__ int   g_cnt[NN];
__device__ int   g_pos[NN];
__device__ int   g_rowptr[NN + 1];
__device__ int   g_blksum[256];
__device__ int   g_csr[EE];
// Pre-transposed, bf16-split weights: [n*128 + k]
__device__ __align__(16) __nv_bfloat16 g_W1hi[D * D];
__device__ __align__(16) __nv_bfloat16 g_W1lo[D * D];
__device__ __align__(16) __nv_bfloat16 g_W2hi[D * D];
__device__ __align__(16) __nv_bfloat16 g_W2lo[D * D];

__device__ __forceinline__ void red_add_v4(float* addr, float4 v) {
    asm volatile("red.global.add.v4.f32 [%0], {%1,%2,%3,%4};"
                 :: "l"(__cvta_generic_to_global(addr)),
                    "f"(v.x), "f"(v.y), "f"(v.z), "f"(v.w)
                 : "memory");
}

__device__ __forceinline__ uint32_t pack_bf2(float a, float b) {
    __nv_bfloat162 t = __floats2bfloat162_rn(a, b);   // x=a (low), y=b (high)
    return *reinterpret_cast<uint32_t*>(&t);
}

// ---------------------------------------------------------------------------
__global__ void k_init() {
    int i = blockIdx.x * blockDim.x + threadIdx.x;
    if (i < NN) g_cnt[i] = 0;
    if (i < NG * D) g_pool[i] = 0.0f;
}

__global__ void k_count(const int* __restrict__ ei) {
    int i = blockIdx.x * blockDim.x + threadIdx.x;
    if (i < EE) atomicAdd(&g_cnt[ei[EE + i]], 1);
}

__global__ void k_scan1() {
    __shared__ int s[SCAN_BLK];
    int gid = blockIdx.x * SCAN_BLK + threadIdx.x;
    int v = (gid < NN) ? g_cnt[gid] : 0;
    s[threadIdx.x] = v;
    __syncthreads();
    #pragma unroll
    for (int off = 1; off < SCAN_BLK; off <<= 1) {
        int t = (threadIdx.x >= off) ? s[threadIdx.x - off] : 0;
        __syncthreads();
        s[threadIdx.x] += t;
        __syncthreads();
    }
    if (gid < NN) g_rowptr[gid + 1] = s[threadIdx.x];
    if (threadIdx.x == SCAN_BLK - 1) g_blksum[blockIdx.x] = s[threadIdx.x];
    if (gid == 0) g_rowptr[0] = 0;
}

__global__ void k_scan2() {
    __shared__ int s[256];
    int v = (threadIdx.x < NBLK) ? g_blksum[threadIdx.x] : 0;
    s[threadIdx.x] = v;
    __syncthreads();
    #pragma unroll
    for (int off = 1; off < 256; off <<= 1) {
        int t = (threadIdx.x >= off) ? s[threadIdx.x - off] : 0;
        __syncthreads();
        s[threadIdx.x] += t;
        __syncthreads();
    }
    if (threadIdx.x < NBLK) g_blksum[threadIdx.x] = s[threadIdx.x] - v;
}

// scan3: finalize rowptr, seed fill cursors, compute dinv.
__global__ void k_scan3() {
    int gid = blockIdx.x * SCAN_BLK + threadIdx.x;
    if (gid < NN) {
        int incl = g_rowptr[gid + 1] + g_blksum[blockIdx.x];
        g_rowptr[gid + 1] = incl;
        int cnt = g_cnt[gid];
        g_pos[gid] = incl - cnt;
        g_dinv[gid] = rsqrtf((float)(cnt + 1));
    }
}

__global__ void k_fill(const int* __restrict__ ei) {
    int i = blockIdx.x * blockDim.x + threadIdx.x;
    if (i < EE) {
        int s = ei[i];
        int d = ei[EE + i];
        g_csr[atomicAdd(&g_pos[d], 1)] = s;
    }
}

// Transpose + bf16-split weights: Wt[n][k] = W[k][n] as (hi, lo)
__global__ void k_prepw(const float* __restrict__ W1, const float* __restrict__ W2) {
    int id = blockIdx.x * blockDim.x + threadIdx.x;
    int w = id >> 14;
    int r = id & 16383;
    int k = r >> 7, n = r & 127;
    float v = (w ? W2 : W1)[k * D + n];
    __nv_bfloat16 hi = __float2bfloat16_rn(v);
    __nv_bfloat16 lo = __float2bfloat16_rn(v - __bfloat162float(hi));
    (w ? g_W2hi : g_W1hi)[n * D + k] = hi;
    (w ? g_W2lo : g_W1lo)[n * D + k] = lo;
}

// Split x into g_Ahi/g_Alo (layer-1 GEMM input). One float4 per thread.
__global__ void k_prepx(const float* __restrict__ x) {
    int i = blockIdx.x * blockDim.x + threadIdx.x;   // float4 index
    if (i >= NN * D / 4) return;
    float4 v = reinterpret_cast<const float4*>(x)[i];
    float hx = __bfloat162float(__float2bfloat16_rn(v.x));
    float hy = __bfloat162float(__float2bfloat16_rn(v.y));
    float hz = __bfloat162float(__float2bfloat16_rn(v.z));
    float hw = __bfloat162float(__float2bfloat16_rn(v.w));
    uint2 hi = make_uint2(pack_bf2(v.x, v.y), pack_bf2(v.z, v.w));
    uint2 lo = make_uint2(pack_bf2(v.x - hx, v.y - hy), pack_bf2(v.z - hz, v.w - hw));
    reinterpret_cast<uint2*>(g_Ahi)[i] = hi;
    reinterpret_cast<uint2*>(g_Alo)[i] = lo;
}

// ---------------------------------------------------------------------------
// Split-bf16 tensor GEMM: bufA(bf16) = dinv[row] * (A @ W).
// A pre-split in g_Ahi/g_Alo. Full K=128 staged once via cp.async. 8 warps.

#define SWZ(x) ((x) ^ (((x) >> 3) & 0x70))
// smem: 4 arrays x 32KB (each = 2 chunks x [128 rows][64 k] bf16, 128B rows)
#define S_AHI 0
#define S_ALO 32768
#define S_BHI 65536
#define S_BLO 98304
#define GEMM_SMEM 131072

__device__ __forceinline__ void cp16(uint32_t dst, const void* src, int srcsize) {
    asm volatile("cp.async.cg.shared.global [%0], [%1], 16, %2;"
                 :: "r"(dst), "l"(src), "r"(srcsize));
}

__device__ __forceinline__ void ldm4(uint32_t* r, uint32_t addr) {
    asm volatile("ldmatrix.sync.aligned.m8n8.x4.shared.b16 {%0,%1,%2,%3}, [%4];"
                 : "=r"(r[0]), "=r"(r[1]), "=r"(r[2]), "=r"(r[3]) : "r"(addr));
}

__device__ __forceinline__ void mma16816(float* c, const uint32_t* a, const uint32_t* b) {
    asm("mma.sync.aligned.m16n8k16.row.col.f32.bf16.bf16.f32 "
        "{%0,%1,%2,%3}, {%4,%5,%6,%7}, {%8,%9}, {%0,%1,%2,%3};"
        : "+f"(c[0]), "+f"(c[1]), "+f"(c[2]), "+f"(c[3])
        : "r"(a[0]), "r"(a[1]), "r"(a[2]), "r"(a[3]), "r"(b[0]), "r"(b[1]));
}

template<int LAYER>   // picks W1 vs W2 (device globals referenced in device code)
__global__ void __launch_bounds__(256, 1)
k_gemm_mma() {
    extern __shared__ char smem[];
    uint32_t sb;
    { uint64_t tmp; asm("cvta.to.shared.u64 %0, %1;" : "=l"(tmp) : "l"(smem)); sb = (uint32_t)tmp; }

    const int t = threadIdx.x;
    const int wid = t >> 5;
    const int lid = t & 31;
    const int row0 = blockIdx.x * 128;
    const int warp_m = wid & 3;
    const int warp_n = wid >> 2;

    const __nv_bfloat16* Whi = (LAYER == 1) ? g_W1hi : g_W2hi;
    const __nv_bfloat16* Wlo = (LAYER == 1) ? g_W1lo : g_W2lo;

    // ---- stage everything with cp.async (zfill OOB rows) ----
    #pragma unroll
    for (int arr = 0; arr < 2; arr++) {
        const __nv_bfloat16* Asrc = arr ? g_Alo : g_Ahi;
        const uint32_t abase = sb + (arr ? S_ALO : S_AHI);
        #pragma unroll
        for (int c = 0; c < 2; c++)
            #pragma unroll
            for (int i = 0; i < 4; i++) {
                int id = t + i * 256;          // 0..1023
                int r  = id >> 3;              // 0..127
                int q  = id & 7;               // 16B granule
                int grow = row0 + r;
                const void* g = Asrc + (size_t)grow * D + c * 64 + q * 8;
                cp16(abase + c * 16384 + SWZ((uint32_t)(r * 128 + q * 16)),
                     g, (grow < NN) ? 16 : 0);
            }
    }
    #pragma unroll
    for (int arr = 0; arr < 2; arr++) {
        const __nv_bfloat16* Bsrc = arr ? Wlo : Whi;
        const uint32_t bbase = sb + (arr ? S_BLO : S_BHI);
        #pragma unroll
        for (int c = 0; c < 2; c++)
            #pragma unroll
            for (int i = 0; i < 4; i++) {
                int id = t + i * 256;
                int n  = id >> 3;
                int q  = id & 7;
                cp16(bbase + c * 16384 + SWZ((uint32_t)(n * 128 + q * 16)),
                     Bsrc + n * D + c * 64 + q * 8, 16);
            }
    }
    asm volatile("cp.async.commit_group;");
    asm volatile("cp.async.wait_group 0;" ::: "memory");
    __syncthreads();

    float acc[2][8][4];
    #pragma unroll
    for (int i = 0; i < 2; i++)
        #pragma unroll
        for (int j = 0; j < 8; j++)
            #pragma unroll
            for (int q = 0; q < 4; q++) acc[i][j][q] = 0.0f;

    // ---- compute: 2 chunks x 4 k-steps of 16 ----
    #pragma unroll
    for (int c = 0; c < 2; c++) {
        const uint32_t co = c * 16384;
        #pragma unroll
        for (int ks = 0; ks < 4; ks++) {
            uint32_t ah[2][4], al[2][4];
            #pragma unroll
            for (int mt = 0; mt < 2; mt++) {
                uint32_t off = SWZ((uint32_t)((warp_m * 32 + mt * 16 + (lid & 15)) * 128
                                              + ks * 32 + (lid >> 4) * 16));
                ldm4(ah[mt], sb + S_AHI + co + off);
                ldm4(al[mt], sb + S_ALO + co + off);
            }
            uint32_t bh[8][2], bl[8][2];
            #pragma unroll
            for (int ntp = 0; ntp < 4; ntp++) {
                uint32_t nrow = (lid & 7) + ((lid >> 4) & 1) * 8;
                uint32_t kb = ((lid >> 3) & 1) * 16;
                uint32_t off = SWZ((uint32_t)((warp_n * 64 + ntp * 16 + nrow) * 128
                                              + ks * 32 + kb));
                uint32_t r[4];
                ldm4(r, sb + S_BHI + co + off);
                bh[2 * ntp][0] = r[0]; bh[2 * ntp][1] = r[1];
                bh[2 * ntp + 1][0] = r[2]; bh[2 * ntp + 1][1] = r[3];
                ldm4(r, sb + S_BLO + co + off);
                bl[2 * ntp][0] = r[0]; bl[2 * ntp][1] = r[1];
                bl[2 * ntp + 1][0] = r[2]; bl[2 * ntp + 1][1] = r[3];
            }
            #pragma unroll
            for (int mt = 0; mt < 2; mt++)
                #pragma unroll
                for (int nt = 0; nt < 8; nt++) {
                    mma16816(acc[mt][nt], ah[mt], bh[nt]);
                    mma16816(acc[mt][nt], ah[mt], bl[nt]);
                    mma16816(acc[mt][nt], al[mt], bh[nt]);
                }
        }
    }

    // ---- epilogue: scale by dinv[row], store bf16 messages ----
    const int g = lid >> 2, tig = lid & 3;
    #pragma unroll
    for (int mt = 0; mt < 2; mt++) {
        int m0 = row0 + warp_m * 32 + mt * 16 + g;
        int m8 = m0 + 8;
        float dv0 = (m0 < NN) ? g_dinv[m0] : 0.f;
        float dv8 = (m8 < NN) ? g_dinv[m8] : 0.f;
        #pragma unroll
        for (int nt = 0; nt < 8; nt++) {
            int col = warp_n * 64 + nt * 8 + tig * 2;
            if (m0 < NN)
                *reinterpret_cast<uint32_t*>(g_bufA + m0 * D + col) =
                    pack_bf2(acc[mt][nt][0] * dv0, acc[mt][nt][1] * dv0);
            if (m8 < NN)
                *reinterpret_cast<uint32_t*>(g_bufA + m8 * D + col) =
                    pack_bf2(acc[mt][nt][2] * dv8, acc[mt][nt][3] * dv8);
        }
    }
}

// ---------------------------------------------------------------------------
// CSR gather over bf16 messages; unpack via shift/mask (exact). Warp per node.
// Lane owns dims [lane*4 .. lane*4+3].
template<bool POOL>
__global__ void __launch_bounds__(256)
k_aggr(const int* __restrict__ batch, const float* __restrict__ bin) {
    int w = (blockIdx.x * blockDim.x + threadIdx.x) >> 5;
    int lane = threadIdx.x & 31;
    if (w >= NN) return;
    const int n = w;

    const uint2* src = reinterpret_cast<const uint2*>(g_bufA);  // 32 uint2/row
    float acc0, acc1, acc2, acc3;
    {
        uint2 u = src[n * 32 + lane];
        acc0 = __uint_as_float(u.x << 16);
        acc1 = __uint_as_float(u.x & 0xFFFF0000u);
        acc2 = __uint_as_float(u.y << 16);
        acc3 = __uint_as_float(u.y & 0xFFFF0000u);
    }
    int beg = g_rowptr[n];
    int end = g_rowptr[n + 1];

    for (int base = beg; base < end; base += 32) {
        int idx = base + lane;
        int s_l = (idx < end) ? g_csr[idx] : 0;
        int cnt = min(32, end - base);
        for (int j = 0; j < cnt; j++) {
            int s = __shfl_sync(0xffffffffu, s_l, j);
            uint2 u = src[s * 32 + lane];
            acc0 += __uint_as_float(u.x << 16);
            acc1 += __uint_as_float(u.x & 0xFFFF0000u);
            acc2 += __uint_as_float(u.y << 16);
            acc3 += __uint_as_float(u.y & 0xFFFF0000u);
        }
    }

    float dv = g_dinv[n];
    float4 bb = reinterpret_cast<const float4*>(bin)[lane];
    float r0 = fmaxf(fmaf(dv, acc0, bb.x), 0.f);
    float r1 = fmaxf(fmaf(dv, acc1, bb.y), 0.f);
    float r2 = fmaxf(fmaf(dv, acc2, bb.z), 0.f);
    float r3 = fmaxf(fmaf(dv, acc3, bb.w), 0.f);

    if (!POOL) {
        // split to bf16 hi/lo -> next GEMM's A input
        float h0 = __bfloat162float(__float2bfloat16_rn(r0));
        float h1 = __bfloat162float(__float2bfloat16_rn(r1));
        float h2 = __bfloat162float(__float2bfloat16_rn(r2));
        float h3 = __bfloat162float(__float2bfloat16_rn(r3));
        reinterpret_cast<uint2*>(g_Ahi)[n * 32 + lane] =
            make_uint2(pack_bf2(r0, r1), pack_bf2(r2, r3));
        reinterpret_cast<uint2*>(g_Alo)[n * 32 + lane] =
            make_uint2(pack_bf2(r0 - h0, r1 - h1), pack_bf2(r2 - h2, r3 - h3));
    } else {
        int g = batch[n];
        red_add_v4(g_pool + g * D + lane * 4, make_float4(r0, r1, r2, r3));
    }
}

// ---------------------------------------------------------------------------
__global__ void k_final(const float* __restrict__ Wl,
                        const float* __restrict__ bl,
                        float* __restrict__ out) {
    __shared__ float p[D];
    int g = blockIdx.x;
    int o = threadIdx.x;
    p[o]      = g_pool[g * D + o];
    p[o + 64] = g_pool[g * D + o + 64];
    __syncthreads();
    float acc = bl[o];
    #pragma unroll 8
    for (int c = 0; c < D; c++)
        acc = fmaf(p[c], Wl[c * OD + o], acc);
    out[g * OD + o] = acc;
}

// ---------------------------------------------------------------------------
extern "C" void kernel_launch(void* const* d_in, const int* in_sizes, int n_in,
                              void* d_out, int out_size) {
    const float* x     = (const float*)d_in[0];
    const int*   ei    = (const int*)d_in[1];      // int32 (JAX x64 disabled)
    const int*   batch = (const int*)d_in[2];
    const float* W1    = (const float*)d_in[3];
    const float* b1    = (const float*)d_in[4];
    const float* W2    = (const float*)d_in[5];
    const float* b2    = (const float*)d_in[6];
    const float* Wl    = (const float*)d_in[7];
    const float* bl    = (const float*)d_in[8];
    float* out = (float*)d_out;

    cudaFuncSetAttribute(k_gemm_mma<1>,
                         cudaFuncAttributeMaxDynamicSharedMemorySize, GEMM_SMEM);
    cudaFuncSetAttribute(k_gemm_mma<2>,
                         cudaFuncAttributeMaxDynamicSharedMemorySize, GEMM_SMEM);

    // CSR build + norms + input/weight prep
    k_init <<<(NN + 255) / 256, 256>>>();
    k_count<<<(EE + 255) / 256, 256>>>(ei);
    k_prepw<<<128, 256>>>(W1, W2);
    k_prepx<<<(NN * D / 4 + 255) / 256, 256>>>(x);
    k_scan1<<<NBLK, SCAN_BLK>>>();
    k_scan2<<<1, 256>>>();
    k_scan3<<<NBLK, SCAN_BLK>>>();
    k_fill <<<(EE + 255) / 256, 256>>>(ei);

    // Layer 1
    k_gemm_mma<1><<<(NN + 127) / 128, 256, GEMM_SMEM>>>();
    k_aggr<false><<<(NN * 32 + 255) / 256, 256>>>(nullptr, b1);

    // Layer 2
    k_gemm_mma<2><<<(NN + 127) / 128, 256, GEMM_SMEM>>>();
    k_aggr<true><<<(NN * 32 + 255) / 256, 256>>>(batch, b2);

    k_final<<<NG, OD>>>(Wl, bl, out);
}

// round 11
// speedup vs baseline: 2.8554x; 1.0424x over previous
#include <cuda_runtime.h>
#include <cuda_bf16.h>
#include <cstdint>

#define NN 100000
#define EE 1600000
#define D  128
#define OD 64
#define NG 512
#define SCAN_BLK 512
#define NBLK ((NN + SCAN_BLK - 1) / SCAN_BLK)   // 196

// Scratch (device globals: allocation-free)
__device__ __align__(16) __nv_bfloat16 g_bufA[NN * D];  // messages (bf16)
__device__ __align__(16) __nv_bfloat16 g_Ahi[NN * D];   // GEMM A input hi
__device__ __align__(16) __nv_bfloat16 g_Alo[NN * D];   // GEMM A input lo
__device__ float g_dinv[NN];
__device__ __align__(16) float g_pool[NG * D];   // zeroed by k_final (self-clean)
__device__ int   g_cnt[NN];                      // zeroed by k_scan3 (self-clean)
__device__ int   g_pos[NN];
__device__ int   g_rowptr[NN + 1];
__device__ int   g_blksum[256];
__device__ int   g_csr[EE];
// Pre-transposed, bf16-split weights: [n*128 + k]
__device__ __align__(16) __nv_bfloat16 g_W1hi[D * D];
__device__ __align__(16) __nv_bfloat16 g_W1lo[D * D];
__device__ __align__(16) __nv_bfloat16 g_W2hi[D * D];
__device__ __align__(16) __nv_bfloat16 g_W2lo[D * D];

__device__ __forceinline__ void red_add_v4(float* addr, float4 v) {
    asm volatile("red.global.add.v4.f32 [%0], {%1,%2,%3,%4};"
                 :: "l"(__cvta_generic_to_global(addr)),
                    "f"(v.x), "f"(v.y), "f"(v.z), "f"(v.w)
                 : "memory");
}

__device__ __forceinline__ uint32_t pack_bf2(float a, float b) {
    __nv_bfloat162 t = __floats2bfloat162_rn(a, b);
    return *reinterpret_cast<uint32_t*>(&t);
}

// ---------------------------------------------------------------------------
// Fused prep: edge-degree count + x split + W transpose/split. Disjoint data,
// blockIdx-branched. g_cnt arrives zeroed (BSS at load / scan3 self-clean).
#define NB_COUNT ((EE + 255) / 256)          // 6250
#define NB_PREPX ((NN * D / 4 + 255) / 256)  // 12500
#define NB_PREPW 128

__global__ void k_prep(const int* __restrict__ ei, const float* __restrict__ x,
                       const float* __restrict__ W1, const float* __restrict__ W2) {
    int b = blockIdx.x;
    if (b < NB_COUNT) {
        int i = b * 256 + threadIdx.x;
        if (i < EE) atomicAdd(&g_cnt[ei[EE + i]], 1);
    } else if (b < NB_COUNT + NB_PREPX) {
        int i = (b - NB_COUNT) * 256 + threadIdx.x;   // float4 index
        if (i < NN * D / 4) {
            float4 v = reinterpret_cast<const float4*>(x)[i];
            float hx = __bfloat162float(__float2bfloat16_rn(v.x));
            float hy = __bfloat162float(__float2bfloat16_rn(v.y));
            float hz = __bfloat162float(__float2bfloat16_rn(v.z));
            float hw = __bfloat162float(__float2bfloat16_rn(v.w));
            reinterpret_cast<uint2*>(g_Ahi)[i] =
                make_uint2(pack_bf2(v.x, v.y), pack_bf2(v.z, v.w));
            reinterpret_cast<uint2*>(g_Alo)[i] =
                make_uint2(pack_bf2(v.x - hx, v.y - hy), pack_bf2(v.z - hz, v.w - hw));
        }
    } else {
        int id = (b - NB_COUNT - NB_PREPX) * 256 + threadIdx.x;   // 0..32767
        int w = id >> 14;
        int r = id & 16383;
        int k = r >> 7, n = r & 127;
        float v = (w ? W2 : W1)[k * D + n];
        __nv_bfloat16 hi = __float2bfloat16_rn(v);
        __nv_bfloat16 lo = __float2bfloat16_rn(v - __bfloat162float(hi));
        (w ? g_W2hi : g_W1hi)[n * D + k] = hi;
        (w ? g_W2lo : g_W1lo)[n * D + k] = lo;
    }
}

// ---------------------------------------------------------------------------
__global__ void k_scan1() {
    __shared__ int s[SCAN_BLK];
    int gid = blockIdx.x * SCAN_BLK + threadIdx.x;
    int v = (gid < NN) ? g_cnt[gid] : 0;
    s[threadIdx.x] = v;
    __syncthreads();
    #pragma unroll
    for (int off = 1; off < SCAN_BLK; off <<= 1) {
        int t = (threadIdx.x >= off) ? s[threadIdx.x - off] : 0;
        __syncthreads();
        s[threadIdx.x] += t;
        __syncthreads();
    }
    if (gid < NN) g_rowptr[gid + 1] = s[threadIdx.x];
    if (threadIdx.x == SCAN_BLK - 1) g_blksum[blockIdx.x] = s[threadIdx.x];
    if (gid == 0) g_rowptr[0] = 0;
}

__global__ void k_scan2() {
    __shared__ int s[256];
    int v = (threadIdx.x < NBLK) ? g_blksum[threadIdx.x] : 0;
    s[threadIdx.x] = v;
    __syncthreads();
    #pragma unroll
    for (int off = 1; off < 256; off <<= 1) {
        int t = (threadIdx.x >= off) ? s[threadIdx.x - off] : 0;
        __syncthreads();
        s[threadIdx.x] += t;
        __syncthreads();
    }
    if (threadIdx.x < NBLK) g_blksum[threadIdx.x] = s[threadIdx.x] - v;
}

// scan3: finalize rowptr, seed cursors, dinv; zero g_cnt for the next launch.
__global__ void k_scan3() {
    int gid = blockIdx.x * SCAN_BLK + threadIdx.x;
    if (gid < NN) {
        int incl = g_rowptr[gid + 1] + g_blksum[blockIdx.x];
        g_rowptr[gid + 1] = incl;
        int cnt = g_cnt[gid];
        g_cnt[gid] = 0;                          // self-clean for next replay
        g_pos[gid] = incl - cnt;
        g_dinv[gid] = rsqrtf((float)(cnt + 1));
    }
}

__global__ void k_fill(const int* __restrict__ ei) {
    int i = blockIdx.x * blockDim.x + threadIdx.x;
    if (i < EE) {
        int s = ei[i];
        int d = ei[EE + i];
        g_csr[atomicAdd(&g_pos[d], 1)] = s;
    }
}

// ---------------------------------------------------------------------------
// Split-bf16 tensor GEMM: bufA(bf16) = dinv[row] * (A @ W).
// A pre-split in g_Ahi/g_Alo. Full K=128 staged once via cp.async. 8 warps.

#define SWZ(x) ((x) ^ (((x) >> 3) & 0x70))
#define S_AHI 0
#define S_ALO 32768
#define S_BHI 65536
#define S_BLO 98304
#define GEMM_SMEM 131072

__device__ __forceinline__ void cp16(uint32_t dst, const void* src, int srcsize) {
    asm volatile("cp.async.cg.shared.global [%0], [%1], 16, %2;"
                 :: "r"(dst), "l"(src), "r"(srcsize));
}

__device__ __forceinline__ void ldm4(uint32_t* r, uint32_t addr) {
    asm volatile("ldmatrix.sync.aligned.m8n8.x4.shared.b16 {%0,%1,%2,%3}, [%4];"
                 : "=r"(r[0]), "=r"(r[1]), "=r"(r[2]), "=r"(r[3]) : "r"(addr));
}

__device__ __forceinline__ void mma16816(float* c, const uint32_t* a, const uint32_t* b) {
    asm("mma.sync.aligned.m16n8k16.row.col.f32.bf16.bf16.f32 "
        "{%0,%1,%2,%3}, {%4,%5,%6,%7}, {%8,%9}, {%0,%1,%2,%3};"
        : "+f"(c[0]), "+f"(c[1]), "+f"(c[2]), "+f"(c[3])
        : "r"(a[0]), "r"(a[1]), "r"(a[2]), "r"(a[3]), "r"(b[0]), "r"(b[1]));
}

template<int LAYER>
__global__ void __launch_bounds__(256, 1)
k_gemm_mma() {
    extern __shared__ char smem[];
    uint32_t sb;
    { uint64_t tmp; asm("cvta.to.shared.u64 %0, %1;" : "=l"(tmp) : "l"(smem)); sb = (uint32_t)tmp; }

    const int t = threadIdx.x;
    const int wid = t >> 5;
    const int lid = t & 31;
    const int row0 = blockIdx.x * 128;
    const int warp_m = wid & 3;
    const int warp_n = wid >> 2;

    const __nv_bfloat16* Whi = (LAYER == 1) ? g_W1hi : g_W2hi;
    const __nv_bfloat16* Wlo = (LAYER == 1) ? g_W1lo : g_W2lo;

    #pragma unroll
    for (int arr = 0; arr < 2; arr++) {
        const __nv_bfloat16* Asrc = arr ? g_Alo : g_Ahi;
        const uint32_t abase = sb + (arr ? S_ALO : S_AHI);
        #pragma unroll
        for (int c = 0; c < 2; c++)
            #pragma unroll
            for (int i = 0; i < 4; i++) {
                int id = t + i * 256;
                int r  = id >> 3;
                int q  = id & 7;
                int grow = row0 + r;
                const void* g = Asrc + (size_t)grow * D + c * 64 + q * 8;
                cp16(abase + c * 16384 + SWZ((uint32_t)(r * 128 + q * 16)),
                     g, (grow < NN) ? 16 : 0);
            }
    }
    #pragma unroll
    for (int arr = 0; arr < 2; arr++) {
        const __nv_bfloat16* Bsrc = arr ? Wlo : Whi;
        const uint32_t bbase = sb + (arr ? S_BLO : S_BHI);
        #pragma unroll
        for (int c = 0; c < 2; c++)
            #pragma unroll
            for (int i = 0; i < 4; i++) {
                int id = t + i * 256;
                int n  = id >> 3;
                int q  = id & 7;
                cp16(bbase + c * 16384 + SWZ((uint32_t)(n * 128 + q * 16)),
                     Bsrc + n * D + c * 64 + q * 8, 16);
            }
    }
    asm volatile("cp.async.commit_group;");
    asm volatile("cp.async.wait_group 0;" ::: "memory");
    __syncthreads();

    float acc[2][8][4];
    #pragma unroll
    for (int i = 0; i < 2; i++)
        #pragma unroll
        for (int j = 0; j < 8; j++)
            #pragma unroll
            for (int q = 0; q < 4; q++) acc[i][j][q] = 0.0f;

    #pragma unroll
    for (int c = 0; c < 2; c++) {
        const uint32_t co = c * 16384;
        #pragma unroll
        for (int ks = 0; ks < 4; ks++) {
            uint32_t ah[2][4], al[2][4];
            #pragma unroll
            for (int mt = 0; mt < 2; mt++) {
                uint32_t off = SWZ((uint32_t)((warp_m * 32 + mt * 16 + (lid & 15)) * 128
                                              + ks * 32 + (lid >> 4) * 16));
                ldm4(ah[mt], sb + S_AHI + co + off);
                ldm4(al[mt], sb + S_ALO + co + off);
            }
            uint32_t bh[8][2], bl[8][2];
            #pragma unroll
            for (int ntp = 0; ntp < 4; ntp++) {
                uint32_t nrow = (lid & 7) + ((lid >> 4) & 1) * 8;
                uint32_t kb = ((lid >> 3) & 1) * 16;
                uint32_t off = SWZ((uint32_t)((warp_n * 64 + ntp * 16 + nrow) * 128
                                              + ks * 32 + kb));
                uint32_t r[4];
                ldm4(r, sb + S_BHI + co + off);
                bh[2 * ntp][0] = r[0]; bh[2 * ntp][1] = r[1];
                bh[2 * ntp + 1][0] = r[2]; bh[2 * ntp + 1][1] = r[3];
                ldm4(r, sb + S_BLO + co + off);
                bl[2 * ntp][0] = r[0]; bl[2 * ntp][1] = r[1];
                bl[2 * ntp + 1][0] = r[2]; bl[2 * ntp + 1][1] = r[3];
            }
            #pragma unroll
            for (int mt = 0; mt < 2; mt++)
                #pragma unroll
                for (int nt = 0; nt < 8; nt++) {
                    mma16816(acc[mt][nt], ah[mt], bh[nt]);
                    mma16816(acc[mt][nt], ah[mt], bl[nt]);
                    mma16816(acc[mt][nt], al[mt], bh[nt]);
                }
        }
    }

    const int g = lid >> 2, tig = lid & 3;
    #pragma unroll
    for (int mt = 0; mt < 2; mt++) {
        int m0 = row0 + warp_m * 32 + mt * 16 + g;
        int m8 = m0 + 8;
        float dv0 = (m0 < NN) ? g_dinv[m0] : 0.f;
        float dv8 = (m8 < NN) ? g_dinv[m8] : 0.f;
        #pragma unroll
        for (int nt = 0; nt < 8; nt++) {
            int col = warp_n * 64 + nt * 8 + tig * 2;
            if (m0 < NN)
                *reinterpret_cast<uint32_t*>(g_bufA + m0 * D + col) =
                    pack_bf2(acc[mt][nt][0] * dv0, acc[mt][nt][1] * dv0);
            if (m8 < NN)
                *reinterpret_cast<uint32_t*>(g_bufA + m8 * D + col) =
                    pack_bf2(acc[mt][nt][2] * dv8, acc[mt][nt][3] * dv8);
        }
    }
}

// ---------------------------------------------------------------------------
// CSR gather over bf16 messages; shift/mask unpack (exact). Warp per node.
// Edge loop unrolled x4 for MLP.
#define BF_ACC4(u0, u1) \
    acc0 += __uint_as_float((u0) << 16);        \
    acc1 += __uint_as_float((u0) & 0xFFFF0000u);\
    acc2 += __uint_as_float((u1) << 16);        \
    acc3 += __uint_as_float((u1) & 0xFFFF0000u);

template<bool POOL>
__global__ void __launch_bounds__(256)
k_aggr(const int* __restrict__ batch, const float* __restrict__ bin) {
    int w = (blockIdx.x * blockDim.x + threadIdx.x) >> 5;
    int lane = threadIdx.x & 31;
    if (w >= NN) return;
    const int n = w;

    const uint2* src = reinterpret_cast<const uint2*>(g_bufA);
    float acc0, acc1, acc2, acc3;
    {
        uint2 u = src[n * 32 + lane];
        acc0 = __uint_as_float(u.x << 16);
        acc1 = __uint_as_float(u.x & 0xFFFF0000u);
        acc2 = __uint_as_float(u.y << 16);
        acc3 = __uint_as_float(u.y & 0xFFFF0000u);
    }
    int beg = g_rowptr[n];
    int end = g_rowptr[n + 1];

    for (int base = beg; base < end; base += 32) {
        int idx = base + lane;
        int s_l = (idx < end) ? g_csr[idx] : 0;
        int cnt = min(32, end - base);
        int j = 0;
        for (; j + 4 <= cnt; j += 4) {
            int s0 = __shfl_sync(0xffffffffu, s_l, j);
            int s1 = __shfl_sync(0xffffffffu, s_l, j + 1);
            int s2 = __shfl_sync(0xffffffffu, s_l, j + 2);
            int s3 = __shfl_sync(0xffffffffu, s_l, j + 3);
            uint2 u0 = src[s0 * 32 + lane];
            uint2 u1 = src[s1 * 32 + lane];
            uint2 u2 = src[s2 * 32 + lane];
            uint2 u3 = src[s3 * 32 + lane];
            BF_ACC4(u0.x, u0.y)
            BF_ACC4(u1.x, u1.y)
            BF_ACC4(u2.x, u2.y)
            BF_ACC4(u3.x, u3.y)
        }
        for (; j < cnt; j++) {
            int s = __shfl_sync(0xffffffffu, s_l, j);
            uint2 u = src[s * 32 + lane];
            BF_ACC4(u.x, u.y)
        }
    }

    float dv = g_dinv[n];
    float4 bb = reinterpret_cast<const float4*>(bin)[lane];
    float r0 = fmaxf(fmaf(dv, acc0, bb.x), 0.f);
    float r1 = fmaxf(fmaf(dv, acc1, bb.y), 0.f);
    float r2 = fmaxf(fmaf(dv, acc2, bb.z), 0.f);
    float r3 = fmaxf(fmaf(dv, acc3, bb.w), 0.f);

    if (!POOL) {
        float h0 = __bfloat162float(__float2bfloat16_rn(r0));
        float h1 = __bfloat162float(__float2bfloat16_rn(r1));
        float h2 = __bfloat162float(__float2bfloat16_rn(r2));
        float h3 = __bfloat162float(__float2bfloat16_rn(r3));
        reinterpret_cast<uint2*>(g_Ahi)[n * 32 + lane] =
            make_uint2(pack_bf2(r0, r1), pack_bf2(r2, r3));
        reinterpret_cast<uint2*>(g_Alo)[n * 32 + lane] =
            make_uint2(pack_bf2(r0 - h0, r1 - h1), pack_bf2(r2 - h2, r3 - h3));
    } else {
        int g = batch[n];
        red_add_v4(g_pool + g * D + lane * 4, make_float4(r0, r1, r2, r3));
    }
}

// ---------------------------------------------------------------------------
// Head: out[g] = pool[g] @ Wl + bl. Zeroes pool row after reading (self-clean).
__global__ void k_final(const float* __restrict__ Wl,
                        const float* __restrict__ bl,
                        float* __restrict__ out) {
    __shared__ float p[D];
    int g = blockIdx.x;
    int o = threadIdx.x;
    p[o]      = g_pool[g * D + o];
    p[o + 64] = g_pool[g * D + o + 64];
    g_pool[g * D + o]      = 0.0f;   // self-clean for next replay
    g_pool[g * D + o + 64] = 0.0f;
    __syncthreads();
    float acc = bl[o];
    #pragma unroll 8
    for (int c = 0; c < D; c++)
        acc = fmaf(p[c], Wl[c * OD + o], acc);
    out[g * OD + o] = acc;
}

// ---------------------------------------------------------------------------
extern "C" void kernel_launch(void* const* d_in, const int* in_sizes, int n_in,
                              void* d_out, int out_size) {
    const float* x     = (const float*)d_in[0];
    const int*   ei    = (const int*)d_in[1];      // int32 (JAX x64 disabled)
    const int*   batch = (const int*)d_in[2];
    const float* W1    = (const float*)d_in[3];
    const float* b1    = (const float*)d_in[4];
    const float* W2    = (const float*)d_in[5];
    const float* b2    = (const float*)d_in[6];
    const float* Wl    = (const float*)d_in[7];
    const float* bl    = (const float*)d_in[8];
    float* out = (float*)d_out;

    cudaFuncSetAttribute(k_gemm_mma<1>,
                         cudaFuncAttributeMaxDynamicSharedMemorySize, GEMM_SMEM);
    cudaFuncSetAttribute(k_gemm_mma<2>,
                         cudaFuncAttributeMaxDynamicSharedMemorySize, GEMM_SMEM);

    // Prep (count + split-x + split-W fused) and CSR build
    k_prep <<<NB_COUNT + NB_PREPX + NB_PREPW, 256>>>(ei, x, W1, W2);
    k_scan1<<<NBLK, SCAN_BLK>>>();
    k_scan2<<<1, 256>>>();
    k_scan3<<<NBLK, SCAN_BLK>>>();
    k_fill <<<(EE + 255) / 256, 256>>>(ei);

    // Layer 1
    k_gemm_mma<1><<<(NN + 127) / 128, 256, GEMM_SMEM>>>();
    k_aggr<false><<<(NN * 32 + 255) / 256, 256>>>(nullptr, b1);

    // Layer 2
    k_gemm_mma<2><<<(NN + 127) / 128, 256, GEMM_SMEM>>>();
    k_aggr<true><<<(NN * 32 + 255) / 256, 256>>>(batch, b2);

    k_final<<<NG, OD>>>(Wl, bl, out);
}

// round 12
// speedup vs baseline: 2.9188x; 1.0222x over previous
#include <cuda_runtime.h>
#include <cuda_bf16.h>
#include <cstdint>

#define NN 100000
#define EE 1600000
#define D  128
#define OD 64
#define NG 512
#define SCAN_BLK 512
#define NBLK ((NN + SCAN_BLK - 1) / SCAN_BLK)   // 196

// Scratch (device globals: allocation-free)
__device__ __align__(16) __nv_bfloat16 g_bufA[NN * D];  // messages (bf16)
__device__ __align__(16) __nv_bfloat16 g_Ahi[NN * D];   // GEMM A input hi
__device__ __align__(16) __nv_bfloat16 g_Alo[NN * D];   // GEMM A input lo
__device__ float g_dinv[NN];
__device__ __align__(16) float g_pool[NG * D];   // zeroed by k_final (self-clean)
__device__ int   g_cnt[NN];                      // zeroed by k_scan3 (self-clean)
__device__ int   g_pos[NN];
__device__ int   g_rowptr[NN + 1];
__device__ int   g_blksum[256];
__device__ int   g_csr[EE];
// Pre-transposed, bf16-split weights: [n*128 + k]
__device__ __align__(16) __nv_bfloat16 g_W1hi[D * D];
__device__ __align__(16) __nv_bfloat16 g_W1lo[D * D];
__device__ __align__(16) __nv_bfloat16 g_W2hi[D * D];
__device__ __align__(16) __nv_bfloat16 g_W2lo[D * D];

__device__ __forceinline__ void red_add_v4(float* addr, float4 v) {
    asm volatile("red.global.add.v4.f32 [%0], {%1,%2,%3,%4};"
                 :: "l"(__cvta_generic_to_global(addr)),
                    "f"(v.x), "f"(v.y), "f"(v.z), "f"(v.w)
                 : "memory");
}

__device__ __forceinline__ uint32_t pack_bf2(float a, float b) {
    __nv_bfloat162 t = __floats2bfloat162_rn(a, b);
    return *reinterpret_cast<uint32_t*>(&t);
}

// ---------------------------------------------------------------------------
__global__ void k_count(const int* __restrict__ ei) {
    int i = blockIdx.x * blockDim.x + threadIdx.x;
    if (i < EE) atomicAdd(&g_cnt[ei[EE + i]], 1);
}

// x split + W transpose/split (side stream; disjoint from CSR chain)
#define NB_PREPX ((NN * D / 4 + 255) / 256)  // 12500
#define NB_PREPW 128

__global__ void k_prepxw(const float* __restrict__ x,
                         const float* __restrict__ W1, const float* __restrict__ W2) {
    int b = blockIdx.x;
    if (b < NB_PREPX) {
        int i = b * 256 + threadIdx.x;   // float4 index
        if (i < NN * D / 4) {
            float4 v = reinterpret_cast<const float4*>(x)[i];
            float hx = __bfloat162float(__float2bfloat16_rn(v.x));
            float hy = __bfloat162float(__float2bfloat16_rn(v.y));
            float hz = __bfloat162float(__float2bfloat16_rn(v.z));
            float hw = __bfloat162float(__float2bfloat16_rn(v.w));
            reinterpret_cast<uint2*>(g_Ahi)[i] =
                make_uint2(pack_bf2(v.x, v.y), pack_bf2(v.z, v.w));
            reinterpret_cast<uint2*>(g_Alo)[i] =
                make_uint2(pack_bf2(v.x - hx, v.y - hy), pack_bf2(v.z - hz, v.w - hw));
        }
    } else {
        int id = (b - NB_PREPX) * 256 + threadIdx.x;   // 0..32767
        int w = id >> 14;
        int r = id & 16383;
        int k = r >> 7, n = r & 127;
        float v = (w ? W2 : W1)[k * D + n];
        __nv_bfloat16 hi = __float2bfloat16_rn(v);
        __nv_bfloat16 lo = __float2bfloat16_rn(v - __bfloat162float(hi));
        (w ? g_W2hi : g_W1hi)[n * D + k] = hi;
        (w ? g_W2lo : g_W1lo)[n * D + k] = lo;
    }
}

// ---------------------------------------------------------------------------
__global__ void k_scan1() {
    __shared__ int s[SCAN_BLK];
    int gid = blockIdx.x * SCAN_BLK + threadIdx.x;
    int v = (gid < NN) ? g_cnt[gid] : 0;
    s[threadIdx.x] = v;
    __syncthreads();
    #pragma unroll
    for (int off = 1; off < SCAN_BLK; off <<= 1) {
        int t = (threadIdx.x >= off) ? s[threadIdx.x - off] : 0;
        __syncthreads();
        s[threadIdx.x] += t;
        __syncthreads();
    }
    if (gid < NN) g_rowptr[gid + 1] = s[threadIdx.x];
    if (threadIdx.x == SCAN_BLK - 1) g_blksum[blockIdx.x] = s[threadIdx.x];
    if (gid == 0) g_rowptr[0] = 0;
}

// scan3: each block computes its own blksum prefix (merged scan2), finalizes
// rowptr, seeds cursors, dinv; zeroes g_cnt for the next graph replay.
__global__ void k_scan3() {
    __shared__ int red[16];
    __shared__ int pref;
    int t = threadIdx.x;

    int v = (t < blockIdx.x) ? g_blksum[t] : 0;   // NBLK=196 < 512
    #pragma unroll
    for (int off = 16; off; off >>= 1) v += __shfl_down_sync(0xffffffffu, v, off);
    if ((t & 31) == 0) red[t >> 5] = v;
    __syncthreads();
    if (t < 32) {
        int s2 = (t < 16) ? red[t] : 0;
        #pragma unroll
        for (int off = 8; off; off >>= 1) s2 += __shfl_down_sync(0xffffffffu, s2, off);
        if (t == 0) pref = s2;
    }
    __syncthreads();

    int gid = blockIdx.x * SCAN_BLK + t;
    if (gid < NN) {
        int incl = g_rowptr[gid + 1] + pref;
        g_rowptr[gid + 1] = incl;
        int cnt = g_cnt[gid];
        g_cnt[gid] = 0;                          // self-clean for next replay
        g_pos[gid] = incl - cnt;
        g_dinv[gid] = rsqrtf((float)(cnt + 1));
    }
}

__global__ void k_fill(const int* __restrict__ ei) {
    int i = blockIdx.x * blockDim.x + threadIdx.x;
    if (i < EE) {
        int s = ei[i];
        int d = ei[EE + i];
        g_csr[atomicAdd(&g_pos[d], 1)] = s;
    }
}

// ---------------------------------------------------------------------------
// Split-bf16 tensor GEMM: bufA(bf16) = dinv[row] * (A @ W).
#define SWZ(x) ((x) ^ (((x) >> 3) & 0x70))
#define S_AHI 0
#define S_ALO 32768
#define S_BHI 65536
#define S_BLO 98304
#define GEMM_SMEM 131072

__device__ __forceinline__ void cp16(uint32_t dst, const void* src, int srcsize) {
    asm volatile("cp.async.cg.shared.global [%0], [%1], 16, %2;"
                 :: "r"(dst), "l"(src), "r"(srcsize));
}

__device__ __forceinline__ void ldm4(uint32_t* r, uint32_t addr) {
    asm volatile("ldmatrix.sync.aligned.m8n8.x4.shared.b16 {%0,%1,%2,%3}, [%4];"
                 : "=r"(r[0]), "=r"(r[1]), "=r"(r[2]), "=r"(r[3]) : "r"(addr));
}

__device__ __forceinline__ void mma16816(float* c, const uint32_t* a, const uint32_t* b) {
    asm("mma.sync.aligned.m16n8k16.row.col.f32.bf16.bf16.f32 "
        "{%0,%1,%2,%3}, {%4,%5,%6,%7}, {%8,%9}, {%0,%1,%2,%3};"
        : "+f"(c[0]), "+f"(c[1]), "+f"(c[2]), "+f"(c[3])
        : "r"(a[0]), "r"(a[1]), "r"(a[2]), "r"(a[3]), "r"(b[0]), "r"(b[1]));
}

template<int LAYER>
__global__ void __launch_bounds__(256, 1)
k_gemm_mma() {
    extern __shared__ char smem[];
    uint32_t sb;
    { uint64_t tmp; asm("cvta.to.shared.u64 %0, %1;" : "=l"(tmp) : "l"(smem)); sb = (uint32_t)tmp; }

    const int t = threadIdx.x;
    const int wid = t >> 5;
    const int lid = t & 31;
    const int row0 = blockIdx.x * 128;
    const int warp_m = wid & 3;
    const int warp_n = wid >> 2;

    const __nv_bfloat16* Whi = (LAYER == 1) ? g_W1hi : g_W2hi;
    const __nv_bfloat16* Wlo = (LAYER == 1) ? g_W1lo : g_W2lo;

    #pragma unroll
    for (int arr = 0; arr < 2; arr++) {
        const __nv_bfloat16* Asrc = arr ? g_Alo : g_Ahi;
        const uint32_t abase = sb + (arr ? S_ALO : S_AHI);
        #pragma unroll
        for (int c = 0; c < 2; c++)
            #pragma unroll
            for (int i = 0; i < 4; i++) {
                int id = t + i * 256;
                int r  = id >> 3;
                int q  = id & 7;
                int grow = row0 + r;
                const void* g = Asrc + (size_t)grow * D + c * 64 + q * 8;
                cp16(abase + c * 16384 + SWZ((uint32_t)(r * 128 + q * 16)),
                     g, (grow < NN) ? 16 : 0);
            }
    }
    #pragma unroll
    for (int arr = 0; arr < 2; arr++) {
        const __nv_bfloat16* Bsrc = arr ? Wlo : Whi;
        const uint32_t bbase = sb + (arr ? S_BLO : S_BHI);
        #pragma unroll
        for (int c = 0; c < 2; c++)
            #pragma unroll
            for (int i = 0; i < 4; i++) {
                int id = t + i * 256;
                int n  = id >> 3;
                int q  = id & 7;
                cp16(bbase + c * 16384 + SWZ((uint32_t)(n * 128 + q * 16)),
                     Bsrc + n * D + c * 64 + q * 8, 16);
            }
    }
    asm volatile("cp.async.commit_group;");
    asm volatile("cp.async.wait_group 0;" ::: "memory");
    __syncthreads();

    float acc[2][8][4];
    #pragma unroll
    for (int i = 0; i < 2; i++)
        #pragma unroll
        for (int j = 0; j < 8; j++)
            #pragma unroll
            for (int q = 0; q < 4; q++) acc[i][j][q] = 0.0f;

    #pragma unroll
    for (int c = 0; c < 2; c++) {
        const uint32_t co = c * 16384;
        #pragma unroll
        for (int ks = 0; ks < 4; ks++) {
            uint32_t ah[2][4], al[2][4];
            #pragma unroll
            for (int mt = 0; mt < 2; mt++) {
                uint32_t off = SWZ((uint32_t)((warp_m * 32 + mt * 16 + (lid & 15)) * 128
                                              + ks * 32 + (lid >> 4) * 16));
                ldm4(ah[mt], sb + S_AHI + co + off);
                ldm4(al[mt], sb + S_ALO + co + off);
            }
            uint32_t bh[8][2], bl[8][2];
            #pragma unroll
            for (int ntp = 0; ntp < 4; ntp++) {
                uint32_t nrow = (lid & 7) + ((lid >> 4) & 1) * 8;
                uint32_t kb = ((lid >> 3) & 1) * 16;
                uint32_t off = SWZ((uint32_t)((warp_n * 64 + ntp * 16 + nrow) * 128
                                              + ks * 32 + kb));
                uint32_t r[4];
                ldm4(r, sb + S_BHI + co + off);
                bh[2 * ntp][0] = r[0]; bh[2 * ntp][1] = r[1];
                bh[2 * ntp + 1][0] = r[2]; bh[2 * ntp + 1][1] = r[3];
                ldm4(r, sb + S_BLO + co + off);
                bl[2 * ntp][0] = r[0]; bl[2 * ntp][1] = r[1];
                bl[2 * ntp + 1][0] = r[2]; bl[2 * ntp + 1][1] = r[3];
            }
            #pragma unroll
            for (int mt = 0; mt < 2; mt++)
                #pragma unroll
                for (int nt = 0; nt < 8; nt++) {
                    mma16816(acc[mt][nt], ah[mt], bh[nt]);
                    mma16816(acc[mt][nt], ah[mt], bl[nt]);
                    mma16816(acc[mt][nt], al[mt], bh[nt]);
                }
        }
    }

    const int g = lid >> 2, tig = lid & 3;
    #pragma unroll
    for (int mt = 0; mt < 2; mt++) {
        int m0 = row0 + warp_m * 32 + mt * 16 + g;
        int m8 = m0 + 8;
        float dv0 = (m0 < NN) ? g_dinv[m0] : 0.f;
        float dv8 = (m8 < NN) ? g_dinv[m8] : 0.f;
        #pragma unroll
        for (int nt = 0; nt < 8; nt++) {
            int col = warp_n * 64 + nt * 8 + tig * 2;
            if (m0 < NN)
                *reinterpret_cast<uint32_t*>(g_bufA + m0 * D + col) =
                    pack_bf2(acc[mt][nt][0] * dv0, acc[mt][nt][1] * dv0);
            if (m8 < NN)
                *reinterpret_cast<uint32_t*>(g_bufA + m8 * D + col) =
                    pack_bf2(acc[mt][nt][2] * dv8, acc[mt][nt][3] * dv8);
        }
    }
}

// ---------------------------------------------------------------------------
// CSR gather over bf16 messages; shift/mask unpack (exact). Warp per node.
#define BF_ACC4(u0, u1) \
    acc0 += __uint_as_float((u0) << 16);        \
    acc1 += __uint_as_float((u0) & 0xFFFF0000u);\
    acc2 += __uint_as_float((u1) << 16);        \
    acc3 += __uint_as_float((u1) & 0xFFFF0000u);

template<bool POOL>
__global__ void __launch_bounds__(256)
k_aggr(const int* __restrict__ batch, const float* __restrict__ bin) {
    int w = (blockIdx.x * blockDim.x + threadIdx.x) >> 5;
    int lane = threadIdx.x & 31;
    if (w >= NN) return;
    const int n = w;

    const uint2* src = reinterpret_cast<const uint2*>(g_bufA);
    float acc0, acc1, acc2, acc3;
    {
        uint2 u = src[n * 32 + lane];
        acc0 = __uint_as_float(u.x << 16);
        acc1 = __uint_as_float(u.x & 0xFFFF0000u);
        acc2 = __uint_as_float(u.y << 16);
        acc3 = __uint_as_float(u.y & 0xFFFF0000u);
    }
    int beg = g_rowptr[n];
    int end = g_rowptr[n + 1];

    for (int base = beg; base < end; base += 32) {
        int idx = base + lane;
        int s_l = (idx < end) ? g_csr[idx] : 0;
        int cnt = min(32, end - base);
        int j = 0;
        for (; j + 4 <= cnt; j += 4) {
            int s0 = __shfl_sync(0xffffffffu, s_l, j);
            int s1 = __shfl_sync(0xffffffffu, s_l, j + 1);
            int s2 = __shfl_sync(0xffffffffu, s_l, j + 2);
            int s3 = __shfl_sync(0xffffffffu, s_l, j + 3);
            uint2 u0 = src[s0 * 32 + lane];
            uint2 u1 = src[s1 * 32 + lane];
            uint2 u2 = src[s2 * 32 + lane];
            uint2 u3 = src[s3 * 32 + lane];
            BF_ACC4(u0.x, u0.y)
            BF_ACC4(u1.x, u1.y)
            BF_ACC4(u2.x, u2.y)
            BF_ACC4(u3.x, u3.y)
        }
        for (; j < cnt; j++) {
            int s = __shfl_sync(0xffffffffu, s_l, j);
            uint2 u = src[s * 32 + lane];
            BF_ACC4(u.x, u.y)
        }
    }

    float dv = g_dinv[n];
    float4 bb = reinterpret_cast<const float4*>(bin)[lane];
    float r0 = fmaxf(fmaf(dv, acc0, bb.x), 0.f);
    float r1 = fmaxf(fmaf(dv, acc1, bb.y), 0.f);
    float r2 = fmaxf(fmaf(dv, acc2, bb.z), 0.f);
    float r3 = fmaxf(fmaf(dv, acc3, bb.w), 0.f);

    if (!POOL) {
        float h0 = __bfloat162float(__float2bfloat16_rn(r0));
        float h1 = __bfloat162float(__float2bfloat16_rn(r1));
        float h2 = __bfloat162float(__float2bfloat16_rn(r2));
        float h3 = __bfloat162float(__float2bfloat16_rn(r3));
        reinterpret_cast<uint2*>(g_Ahi)[n * 32 + lane] =
            make_uint2(pack_bf2(r0, r1), pack_bf2(r2, r3));
        reinterpret_cast<uint2*>(g_Alo)[n * 32 + lane] =
            make_uint2(pack_bf2(r0 - h0, r1 - h1), pack_bf2(r2 - h2, r3 - h3));
    } else {
        int g = batch[n];
        red_add_v4(g_pool + g * D + lane * 4, make_float4(r0, r1, r2, r3));
    }
}

// ---------------------------------------------------------------------------
__global__ void k_final(const float* __restrict__ Wl,
                        const float* __restrict__ bl,
                        float* __restrict__ out) {
    __shared__ float p[D];
    int g = blockIdx.x;
    int o = threadIdx.x;
    p[o]      = g_pool[g * D + o];
    p[o + 64] = g_pool[g * D + o + 64];
    g_pool[g * D + o]      = 0.0f;   // self-clean for next replay
    g_pool[g * D + o + 64] = 0.0f;
    __syncthreads();
    float acc = bl[o];
    #pragma unroll 8
    for (int c = 0; c < D; c++)
        acc = fmaf(p[c], Wl[c * OD + o], acc);
    out[g * OD + o] = acc;
}

// ---------------------------------------------------------------------------
extern "C" void kernel_launch(void* const* d_in, const int* in_sizes, int n_in,
                              void* d_out, int out_size) {
    const float* x     = (const float*)d_in[0];
    const int*   ei    = (const int*)d_in[1];      // int32 (JAX x64 disabled)
    const int*   batch = (const int*)d_in[2];
    const float* W1    = (const float*)d_in[3];
    const float* b1    = (const float*)d_in[4];
    const float* W2    = (const float*)d_in[5];
    const float* b2    = (const float*)d_in[6];
    const float* Wl    = (const float*)d_in[7];
    const float* bl    = (const float*)d_in[8];
    float* out = (float*)d_out;

    cudaFuncSetAttribute(k_gemm_mma<1>,
                         cudaFuncAttributeMaxDynamicSharedMemorySize, GEMM_SMEM);
    cudaFuncSetAttribute(k_gemm_mma<2>,
                         cudaFuncAttributeMaxDynamicSharedMemorySize, GEMM_SMEM);

    cudaStream_t side;
    cudaStreamCreateWithFlags(&side, cudaStreamNonBlocking);
    cudaEvent_t e0, e1, e2;
    cudaEventCreateWithFlags(&e0, cudaEventDisableTiming);
    cudaEventCreateWithFlags(&e1, cudaEventDisableTiming);
    cudaEventCreateWithFlags(&e2, cudaEventDisableTiming);

    // Fork: side stream does dense prep (x/W split) concurrent with CSR build.
    cudaEventRecord(e0, 0);
    cudaStreamWaitEvent(side, e0, 0);
    k_prepxw<<<NB_PREPX + NB_PREPW, 256, 0, side>>>(x, W1, W2);

    // CSR chain on main (capture) stream
    k_count<<<(EE + 255) / 256, 256>>>(ei);
    k_scan1<<<NBLK, SCAN_BLK>>>();
    k_scan3<<<NBLK, SCAN_BLK>>>();          // merged scan2+scan3
    cudaEventRecord(e1, 0);

    // GEMM1 on side (needs prepxw + dinv from scan3), concurrent with fill
    cudaStreamWaitEvent(side, e1, 0);
    k_gemm_mma<1><<<(NN + 127) / 128, 256, GEMM_SMEM, side>>>();
    cudaEventRecord(e2, side);

    k_fill<<<(EE + 255) / 256, 256>>>(ei);  // main stream

    // Join: aggr1 needs csr (main) + bufA (side gemm1)
    cudaStreamWaitEvent(0, e2, 0);
    k_aggr<false><<<(NN * 32 + 255) / 256, 256>>>(nullptr, b1);

    // Layer 2
    k_gemm_mma<2><<<(NN + 127) / 128, 256, GEMM_SMEM>>>();
    k_aggr<true><<<(NN * 32 + 255) / 256, 256>>>(batch, b2);

    k_final<<<NG, OD>>>(Wl, bl, out);

    cudaEventDestroy(e0);
    cudaEventDestroy(e1);
    cudaEventDestroy(e2);
    cudaStreamDestroy(side);
}